// round 4
// baseline (speedup 1.0000x reference)
#include <cuda_runtime.h>
#include <cuda_bf16.h>
#include <math.h>

#define NN 50000
#define EE 800000
#define ET 850000      // EE + NN self loops
#define FIN 128
#define HC 256         // HEADS*HID
#define NG 500
#define SLOPE 0.2f
#define BNEPS 1e-5f

// ---------------- scratch (device globals; no runtime allocation) -------------
__device__ __align__(256) float  g_h[(size_t)NN * HC];   // GEMM output
__device__ __align__(256) float  g_y[(size_t)NN * HC];   // layer output
__device__ float4 g_as[NN];
__device__ float4 g_ad[NN];
__device__ float4 g_e[ET];
__device__ int    g_deg[NN];
__device__ int    g_rowptr[NN + 1];
__device__ int    g_cursor[NN];
__device__ int    g_eid[ET];
__device__ __align__(256) float  g_pooled[NG * HC];
// normalized int32 indices (robust to int32/int64 input dtype)
__device__ int    g_src[EE];
__device__ int    g_dst[EE];
__device__ int    g_batch[NN];
__device__ int    g_is64;

// ---------------- dtype detect + index normalization ---------------------------
// If edge_index is int64 (values in [0, 50000) << 2^31), every odd 32-bit word
// of the buffer is zero. If int32, odd words are random node ids. Sample 1024.
__global__ void detect_kernel(const unsigned* __restrict__ eiw, int* __restrict__ is64) {
    __shared__ int s_any;
    if (threadIdx.x == 0) s_any = 0;
    __syncthreads();
    unsigned v = eiw[threadIdx.x * 2 + 1];   // odd words of first 2048 words
    if (v != 0u) atomicOr(&s_any, 1);
    __syncthreads();
    if (threadIdx.x == 0) *is64 = s_any ? 0 : 1;
}

__global__ void conv_edges_kernel(const void* __restrict__ ei,
                                  const int* __restrict__ is64,
                                  int* __restrict__ src, int* __restrict__ dst) {
    int eid = blockIdx.x * blockDim.x + threadIdx.x;
    if (eid >= EE) return;
    if (*is64) {
        const long long* p = (const long long*)ei;
        src[eid] = (int)p[eid];
        dst[eid] = (int)p[EE + eid];
    } else {
        const int* p = (const int*)ei;
        src[eid] = p[eid];
        dst[eid] = p[EE + eid];
    }
}

__global__ void conv_batch_kernel(const void* __restrict__ b,
                                  const int* __restrict__ is64,
                                  int* __restrict__ out) {
    int i = blockIdx.x * blockDim.x + threadIdx.x;
    if (i >= NN) return;
    out[i] = (*is64) ? (int)((const long long*)b)[i] : ((const int*)b)[i];
}

// ---------------- CSR build ---------------------------------------------------
__global__ void zero_deg_kernel(int* __restrict__ deg) {
    int i = blockIdx.x * blockDim.x + threadIdx.x;
    if (i < NN) deg[i] = 0;
}

__global__ void count_kernel(const int* __restrict__ edst, int* __restrict__ deg) {
    int eid = blockIdx.x * blockDim.x + threadIdx.x;
    if (eid >= ET) return;
    int d = (eid < EE) ? edst[eid] : (eid - EE);
    atomicAdd(&deg[d], 1);
}

__global__ void scan_kernel(const int* __restrict__ deg, int* __restrict__ rowptr) {
    __shared__ int sdata[1024];
    __shared__ int s_carry;
    int tid = threadIdx.x;
    if (tid == 0) s_carry = 0;
    __syncthreads();
    for (int base = 0; base < NN; base += 1024) {
        int i = base + tid;
        int v = (i < NN) ? deg[i] : 0;
        sdata[tid] = v;
        __syncthreads();
        for (int off = 1; off < 1024; off <<= 1) {
            int t = (tid >= off) ? sdata[tid - off] : 0;
            __syncthreads();
            sdata[tid] += t;
            __syncthreads();
        }
        if (i < NN) rowptr[i + 1] = sdata[tid] + s_carry;
        __syncthreads();
        if (tid == 0) s_carry += sdata[1023];
        __syncthreads();
    }
    if (tid == 0) rowptr[0] = 0;
}

__global__ void cursor_kernel(const int* __restrict__ rowptr, int* __restrict__ cursor) {
    int i = blockIdx.x * blockDim.x + threadIdx.x;
    if (i < NN) cursor[i] = rowptr[i];
}

__global__ void fill_kernel(const int* __restrict__ edst,
                            int* __restrict__ cursor, int* __restrict__ eidbuf) {
    int eid = blockIdx.x * blockDim.x + threadIdx.x;
    if (eid >= ET) return;
    int d = (eid < EE) ? edst[eid] : (eid - EE);
    int pos = atomicAdd(&cursor[d], 1);
    eidbuf[pos] = eid;
}

// ---------------- SGEMM: C = A[M,K] @ B[K,256] --------------------------------
#define BM 128
#define BN 128
#define BK 8
#define TM 8
#define TN 8

__global__ __launch_bounds__(256) void sgemm_kernel(const float* __restrict__ A,
                                                    const float* __restrict__ B,
                                                    float* __restrict__ C,
                                                    int M, int K) {
    const int Nc = HC;
    __shared__ float As[BK][BM];
    __shared__ float Bs[BK][BN];

    int tid = threadIdx.x;
    int cRow = blockIdx.y, cCol = blockIdx.x;
    int tRow = tid / (BN / TN);
    int tCol = tid % (BN / TN);

    int aRow = tid / 2;
    int aCol = (tid & 1) * 4;
    int bRow = tid / 32;
    int bCol = (tid & 31) * 4;

    float acc[TM][TN];
#pragma unroll
    for (int i = 0; i < TM; i++)
#pragma unroll
        for (int j = 0; j < TN; j++) acc[i][j] = 0.f;

    float regM[TM], regN[TN];
    int rowBase = cRow * BM;

    for (int k0 = 0; k0 < K; k0 += BK) {
        int gr = rowBase + aRow;
        float4 av = make_float4(0.f, 0.f, 0.f, 0.f);
        if (gr < M) av = *(const float4*)(A + (size_t)gr * K + k0 + aCol);
        As[aCol + 0][aRow] = av.x;
        As[aCol + 1][aRow] = av.y;
        As[aCol + 2][aRow] = av.z;
        As[aCol + 3][aRow] = av.w;

        float4 bv = *(const float4*)(B + (size_t)(k0 + bRow) * Nc + cCol * BN + bCol);
        Bs[bRow][bCol + 0] = bv.x;
        Bs[bRow][bCol + 1] = bv.y;
        Bs[bRow][bCol + 2] = bv.z;
        Bs[bRow][bCol + 3] = bv.w;
        __syncthreads();

#pragma unroll
        for (int kk = 0; kk < BK; kk++) {
#pragma unroll
            for (int i = 0; i < TM; i++) regM[i] = As[kk][tRow * TM + i];
#pragma unroll
            for (int j = 0; j < TN; j++) regN[j] = Bs[kk][tCol * TN + j];
#pragma unroll
            for (int i = 0; i < TM; i++)
#pragma unroll
                for (int j = 0; j < TN; j++) acc[i][j] = fmaf(regM[i], regN[j], acc[i][j]);
        }
        __syncthreads();
    }

#pragma unroll
    for (int i = 0; i < TM; i++) {
        int r = rowBase + tRow * TM + i;
        if (r >= M) continue;
#pragma unroll
        for (int j = 0; j < TN; j += 4) {
            float4 v = make_float4(acc[i][j], acc[i][j + 1], acc[i][j + 2], acc[i][j + 3]);
            *(float4*)(C + (size_t)r * Nc + cCol * BN + tCol * TN + j) = v;
        }
    }
}

// ---------------- per-node attention logits -----------------------------------
__global__ void asad_kernel(const float* __restrict__ h,
                            const float* __restrict__ att_src,
                            const float* __restrict__ att_dst,
                            float4* __restrict__ as_out,
                            float4* __restrict__ ad_out) {
    int warp = (blockIdx.x * blockDim.x + threadIdx.x) >> 5;
    int lid = threadIdx.x & 31;
    if (warp >= NN) return;
    const float* hr = h + (size_t)warp * HC;
    float ps[4] = {0.f, 0.f, 0.f, 0.f};
    float pd[4] = {0.f, 0.f, 0.f, 0.f};
#pragma unroll
    for (int k = 0; k < 8; k++) {
        int c = lid + 32 * k;
        float v = hr[c];
        ps[k >> 1] = fmaf(v, att_src[c], ps[k >> 1]);
        pd[k >> 1] = fmaf(v, att_dst[c], pd[k >> 1]);
    }
#pragma unroll
    for (int off = 16; off; off >>= 1) {
#pragma unroll
        for (int hh = 0; hh < 4; hh++) {
            ps[hh] += __shfl_xor_sync(0xFFFFFFFFu, ps[hh], off);
            pd[hh] += __shfl_xor_sync(0xFFFFFFFFu, pd[hh], off);
        }
    }
    if (lid == 0) {
        as_out[warp] = make_float4(ps[0], ps[1], ps[2], ps[3]);
        ad_out[warp] = make_float4(pd[0], pd[1], pd[2], pd[3]);
    }
}

// ---------------- per-edge leaky-relu logits ----------------------------------
__global__ void edge_kernel(const int* __restrict__ esrc,
                            const int* __restrict__ edst,
                            const float4* __restrict__ as_in,
                            const float4* __restrict__ ad_in,
                            float4* __restrict__ e_out) {
    int eid = blockIdx.x * blockDim.x + threadIdx.x;
    if (eid >= ET) return;
    int s, d;
    if (eid < EE) { s = esrc[eid]; d = edst[eid]; }
    else          { s = eid - EE; d = s; }
    float4 a = as_in[s];
    float4 b = ad_in[d];
    float4 e;
    float v;
    v = a.x + b.x; e.x = (v > 0.f) ? v : SLOPE * v;
    v = a.y + b.y; e.y = (v > 0.f) ? v : SLOPE * v;
    v = a.z + b.z; e.z = (v > 0.f) ? v : SLOPE * v;
    v = a.w + b.w; e.w = (v > 0.f) ? v : SLOPE * v;
    e_out[eid] = e;
}

// ---------------- node-centric softmax + aggregation + bias + relu + BN -------
__global__ __launch_bounds__(128) void agg_kernel(const int* __restrict__ esrc,
                                                  const float* __restrict__ h,
                                                  const float4* __restrict__ e_in,
                                                  const int* __restrict__ rowptr,
                                                  const int* __restrict__ eidbuf,
                                                  float* __restrict__ y,
                                                  const float* __restrict__ bias,
                                                  const float* __restrict__ gam,
                                                  const float* __restrict__ bet,
                                                  const float* __restrict__ rmean,
                                                  const float* __restrict__ rvar) {
    int warp = (blockIdx.x * blockDim.x + threadIdx.x) >> 5;
    int lid = threadIdx.x & 31;
    if (warp >= NN) return;
    int beg = rowptr[warp], end = rowptr[warp + 1];

    float m[4], s[4];
#pragma unroll
    for (int hh = 0; hh < 4; hh++) { m[hh] = -1e30f; s[hh] = 0.f; }

    for (int j = beg + lid; j < end; j += 32) {
        int eid = eidbuf[j];
        float4 e4 = e_in[eid];
        float ev[4] = {e4.x, e4.y, e4.z, e4.w};
#pragma unroll
        for (int hh = 0; hh < 4; hh++) {
            float mn = fmaxf(m[hh], ev[hh]);
            s[hh] = s[hh] * __expf(m[hh] - mn) + __expf(ev[hh] - mn);
            m[hh] = mn;
        }
    }
#pragma unroll
    for (int off = 16; off; off >>= 1) {
#pragma unroll
        for (int hh = 0; hh < 4; hh++) {
            float mo = __shfl_xor_sync(0xFFFFFFFFu, m[hh], off);
            float so = __shfl_xor_sync(0xFFFFFFFFu, s[hh], off);
            float mn = fmaxf(m[hh], mo);
            s[hh] = s[hh] * __expf(m[hh] - mn) + so * __expf(mo - mn);
            m[hh] = mn;
        }
    }
    float inv[4];
#pragma unroll
    for (int hh = 0; hh < 4; hh++) inv[hh] = 1.f / s[hh];

    float acc[8] = {0.f, 0.f, 0.f, 0.f, 0.f, 0.f, 0.f, 0.f};
    for (int j = beg; j < end; j++) {
        int eid = eidbuf[j];                       // warp-uniform (broadcast)
        int src = (eid < EE) ? esrc[eid] : (eid - EE);
        float4 e4 = e_in[eid];
        float al[4] = {__expf(e4.x - m[0]) * inv[0], __expf(e4.y - m[1]) * inv[1],
                       __expf(e4.z - m[2]) * inv[2], __expf(e4.w - m[3]) * inv[3]};
        const float* hs = h + (size_t)src * HC;
#pragma unroll
        for (int k = 0; k < 8; k++)
            acc[k] = fmaf(hs[lid + 32 * k], al[k >> 1], acc[k]);
    }

    size_t ob = (size_t)warp * HC;
#pragma unroll
    for (int k = 0; k < 8; k++) {
        int c = lid + 32 * k;
        float v = acc[k] + bias[c];
        v = fmaxf(v, 0.f);
        v = (v - rmean[c]) * rsqrtf(rvar[c] + BNEPS) * gam[c] + bet[c];
        y[ob + c] = v;
    }
}

// ---------------- pooling ------------------------------------------------------
__device__ __forceinline__ int lowerb(const int* b, int n, int key) {
    int lo = 0, hi = n;
    while (lo < hi) {
        int mid = (lo + hi) >> 1;
        if (b[mid] < key) lo = mid + 1; else hi = mid;
    }
    return lo;
}

__global__ void pool_kernel(const int* __restrict__ batch,
                            const float* __restrict__ y,
                            float* __restrict__ pooled) {
    int g = blockIdx.x;
    int c = threadIdx.x;     // 256
    __shared__ int s_lo, s_hi;
    if (c == 0) {
        s_lo = lowerb(batch, NN, g);
        s_hi = lowerb(batch, NN, g + 1);
    }
    __syncthreads();
    float sum = 0.f;
    for (int n = s_lo; n < s_hi; n++) sum += y[(size_t)n * HC + c];
    int cnt = s_hi - s_lo;
    float denom = (cnt > 0) ? (float)cnt : 1.f;
    pooled[g * HC + c] = sum / denom;
}

// ---------------- MLP head -----------------------------------------------------
__global__ void head_kernel(const float* __restrict__ pooled,
                            const float* __restrict__ lw1, const float* __restrict__ lb1,
                            const float* __restrict__ lw2, const float* __restrict__ lb2,
                            float* __restrict__ out) {
    int g = blockIdx.x;
    int j = threadIdx.x;     // 128
    __shared__ float sp[256];
    __shared__ float r0[128], r1[128];
    sp[j] = pooled[g * HC + j];
    sp[j + 128] = pooled[g * HC + 128 + j];
    __syncthreads();
    float z = lb1[j];
#pragma unroll 4
    for (int k = 0; k < 256; k++) z = fmaf(sp[k], lw1[k * 128 + j], z);
    z = fmaxf(z, 0.f);
    r0[j] = z * lw2[j * 2 + 0];
    r1[j] = z * lw2[j * 2 + 1];
    __syncthreads();
    for (int off = 64; off; off >>= 1) {
        if (j < off) { r0[j] += r0[j + off]; r1[j] += r1[j + off]; }
        __syncthreads();
    }
    if (j == 0) {
        out[g * 2 + 0] = r0[0] + lb2[0];
        out[g * 2 + 1] = r1[0] + lb2[1];
    }
}

// ---------------- launcher ------------------------------------------------------
extern "C" void kernel_launch(void* const* d_in, const int* in_sizes, int n_in,
                              void* d_out, int out_size) {
    const float* x        = (const float*)d_in[0];
    const void*  ei       = d_in[1];                 // int32 or int64 (auto-detected)
    const void*  batchraw = d_in[2];
    const float* W1       = (const float*)d_in[3];
    const float* att_src1 = (const float*)d_in[4];
    const float* att_dst1 = (const float*)d_in[5];
    const float* b1       = (const float*)d_in[6];
    const float* g1       = (const float*)d_in[7];
    const float* be1      = (const float*)d_in[8];
    const float* rm1      = (const float*)d_in[9];
    const float* rv1      = (const float*)d_in[10];
    const float* W2       = (const float*)d_in[11];
    const float* att_src2 = (const float*)d_in[12];
    const float* att_dst2 = (const float*)d_in[13];
    const float* b2       = (const float*)d_in[14];
    const float* g2       = (const float*)d_in[15];
    const float* be2      = (const float*)d_in[16];
    const float* rm2      = (const float*)d_in[17];
    const float* rv2      = (const float*)d_in[18];
    const float* lw1      = (const float*)d_in[19];
    const float* lb1      = (const float*)d_in[20];
    const float* lw2      = (const float*)d_in[21];
    const float* lb2      = (const float*)d_in[22];

    // resolve scratch symbol addresses (host API; capture-safe, no allocation)
    float*  p_h = nullptr;  float*  p_y = nullptr;  float4* p_as = nullptr;
    float4* p_ad = nullptr; float4* p_e = nullptr;  int* p_deg = nullptr;
    int* p_rowptr = nullptr; int* p_cursor = nullptr; int* p_eid = nullptr;
    float* p_pooled = nullptr; int* p_src = nullptr; int* p_dst = nullptr;
    int* p_batch = nullptr; int* p_is64 = nullptr;
    cudaGetSymbolAddress((void**)&p_h, g_h);
    cudaGetSymbolAddress((void**)&p_y, g_y);
    cudaGetSymbolAddress((void**)&p_as, g_as);
    cudaGetSymbolAddress((void**)&p_ad, g_ad);
    cudaGetSymbolAddress((void**)&p_e, g_e);
    cudaGetSymbolAddress((void**)&p_deg, g_deg);
    cudaGetSymbolAddress((void**)&p_rowptr, g_rowptr);
    cudaGetSymbolAddress((void**)&p_cursor, g_cursor);
    cudaGetSymbolAddress((void**)&p_eid, g_eid);
    cudaGetSymbolAddress((void**)&p_pooled, g_pooled);
    cudaGetSymbolAddress((void**)&p_src, g_src);
    cudaGetSymbolAddress((void**)&p_dst, g_dst);
    cudaGetSymbolAddress((void**)&p_batch, g_batch);
    cudaGetSymbolAddress((void**)&p_is64, g_is64);

    // normalize indices to int32
    detect_kernel<<<1, 1024>>>((const unsigned*)ei, p_is64);
    conv_edges_kernel<<<(EE + 255) / 256, 256>>>(ei, p_is64, p_src, p_dst);
    conv_batch_kernel<<<(NN + 255) / 256, 256>>>(batchraw, p_is64, p_batch);

    // CSR-by-destination build
    zero_deg_kernel<<<(NN + 255) / 256, 256>>>(p_deg);
    count_kernel<<<(ET + 255) / 256, 256>>>(p_dst, p_deg);
    scan_kernel<<<1, 1024>>>(p_deg, p_rowptr);
    cursor_kernel<<<(NN + 255) / 256, 256>>>(p_rowptr, p_cursor);
    fill_kernel<<<(ET + 255) / 256, 256>>>(p_dst, p_cursor, p_eid);

    dim3 ggrid(HC / BN, (NN + BM - 1) / BM);
    int aggBlocks = (NN * 32 + 127) / 128;
    int warpBlocks = (NN * 32 + 255) / 256;

    // ---- layer 1 ----
    sgemm_kernel<<<ggrid, 256>>>(x, W1, p_h, NN, FIN);
    asad_kernel<<<warpBlocks, 256>>>(p_h, att_src1, att_dst1, p_as, p_ad);
    edge_kernel<<<(ET + 255) / 256, 256>>>(p_src, p_dst, p_as, p_ad, p_e);
    agg_kernel<<<aggBlocks, 128>>>(p_src, p_h, p_e, p_rowptr, p_eid, p_y,
                                   b1, g1, be1, rm1, rv1);

    // ---- layer 2 ----
    sgemm_kernel<<<ggrid, 256>>>(p_y, W2, p_h, NN, HC);
    asad_kernel<<<warpBlocks, 256>>>(p_h, att_src2, att_dst2, p_as, p_ad);
    edge_kernel<<<(ET + 255) / 256, 256>>>(p_src, p_dst, p_as, p_ad, p_e);
    agg_kernel<<<aggBlocks, 128>>>(p_src, p_h, p_e, p_rowptr, p_eid, p_y,
                                   b2, g2, be2, rm2, rv2);

    // ---- pool + head ----
    pool_kernel<<<NG, 256>>>(p_batch, p_y, p_pooled);
    head_kernel<<<NG, 128>>>(p_pooled, lw1, lb1, lw2, lb2, (float*)d_out);
}

// round 5
// speedup vs baseline: 1.0796x; 1.0796x over previous
#include <cuda_runtime.h>
#include <cuda_bf16.h>
#include <math.h>

#define NN 50000
#define EE 800000
#define ET 850000      // EE + NN self loops
#define FIN 128
#define HC 256         // HEADS*HID
#define NG 500
#define SLOPE 0.2f
#define BNEPS 1e-5f

// ---------------- scratch (device globals; no runtime allocation) -------------
__device__ __align__(256) float  g_h[(size_t)NN * HC];   // GEMM output
__device__ __align__(256) float  g_y[(size_t)NN * HC];   // layer output
__device__ float4 g_as[NN];
__device__ float4 g_ad[NN];
__device__ float4 g_esort[ET];     // edge logits in CSR order
__device__ int    g_srcsort[ET];   // src node per CSR slot
__device__ int    g_dstsort[ET];   // dst node per CSR slot
__device__ int    g_deg[NN];
__device__ int    g_rowptr[NN + 1];
__device__ int    g_cursor[NN];
__device__ __align__(256) float  g_pooled[NG * HC];
__device__ int    g_src[EE];
__device__ int    g_dst[EE];
__device__ int    g_batch[NN];
__device__ int    g_is64;

// ---------------- dtype detect ------------------------------------------------
__global__ void detect_kernel(const unsigned* __restrict__ eiw, int* __restrict__ is64) {
    __shared__ int s_any;
    if (threadIdx.x == 0) s_any = 0;
    __syncthreads();
    unsigned v = eiw[threadIdx.x * 2 + 1];   // odd words: zero iff int64 little-endian
    if (v != 0u) atomicOr(&s_any, 1);
    __syncthreads();
    if (threadIdx.x == 0) *is64 = s_any ? 0 : 1;
}

// ---------------- combined prep: index conversion + batch + zero deg -----------
__global__ void prep_kernel(const void* __restrict__ ei, const void* __restrict__ b,
                            const int* __restrict__ is64,
                            int* __restrict__ src, int* __restrict__ dst,
                            int* __restrict__ batch, int* __restrict__ deg) {
    int i = blockIdx.x * blockDim.x + threadIdx.x;
    int w = *is64;
    if (i < EE) {
        if (w) {
            const long long* p = (const long long*)ei;
            src[i] = (int)p[i];
            dst[i] = (int)p[EE + i];
        } else {
            const int* p = (const int*)ei;
            src[i] = p[i];
            dst[i] = p[EE + i];
        }
    }
    if (i < NN) {
        batch[i] = w ? (int)((const long long*)b)[i] : ((const int*)b)[i];
        deg[i] = 0;
    }
}

// ---------------- CSR build ---------------------------------------------------
__global__ void count_kernel(const int* __restrict__ edst, int* __restrict__ deg) {
    int eid = blockIdx.x * blockDim.x + threadIdx.x;
    if (eid >= ET) return;
    int d = (eid < EE) ? edst[eid] : (eid - EE);
    atomicAdd(&deg[d], 1);
}

__global__ void scan_kernel(const int* __restrict__ deg, int* __restrict__ rowptr,
                            int* __restrict__ cursor) {
    __shared__ int sdata[1024];
    __shared__ int s_carry;
    int tid = threadIdx.x;
    if (tid == 0) s_carry = 0;
    __syncthreads();
    for (int base = 0; base < NN; base += 1024) {
        int i = base + tid;
        int v = (i < NN) ? deg[i] : 0;
        sdata[tid] = v;
        __syncthreads();
        for (int off = 1; off < 1024; off <<= 1) {
            int t = (tid >= off) ? sdata[tid - off] : 0;
            __syncthreads();
            sdata[tid] += t;
            __syncthreads();
        }
        if (i < NN) {
            rowptr[i + 1] = sdata[tid] + s_carry;
            cursor[i] = sdata[tid] + s_carry - v;   // exclusive prefix
        }
        __syncthreads();
        if (tid == 0) s_carry += sdata[1023];
        __syncthreads();
    }
    if (tid == 0) rowptr[0] = 0;
}

__global__ void fill_kernel(const int* __restrict__ esrc, const int* __restrict__ edst,
                            int* __restrict__ cursor,
                            int* __restrict__ srcsort, int* __restrict__ dstsort) {
    int eid = blockIdx.x * blockDim.x + threadIdx.x;
    if (eid >= ET) return;
    int s, d;
    if (eid < EE) { s = esrc[eid]; d = edst[eid]; }
    else          { s = eid - EE; d = s; }
    int pos = atomicAdd(&cursor[d], 1);
    srcsort[pos] = s;
    dstsort[pos] = d;
}

// ---------------- SGEMM: C = A[M,K] @ B[K,256], double-buffered BK=16 ----------
#define BM 128
#define BN 128
#define BKK 16

__global__ __launch_bounds__(256, 2) void sgemm_kernel(const float* __restrict__ A,
                                                       const float* __restrict__ B,
                                                       float* __restrict__ C,
                                                       int M, int K) {
    __shared__ float As[2][BKK][BM];
    __shared__ float Bs[2][BKK][BN];
    const int Nc = HC;

    int tid = threadIdx.x;
    int cRow = blockIdx.y, cCol = blockIdx.x;
    int rowBase = cRow * BM;

    int aRow = tid >> 2;            // 0..63
    int aCol = (tid & 3) << 2;      // 0,4,8,12
    int bRow = tid >> 5;            // 0..7
    int bCol = (tid & 31) << 2;     // 0..124
    int tRow = tid >> 4;            // 0..15
    int tCol = tid & 15;            // 0..15

    int gr0 = rowBase + aRow;
    int gr1 = gr0 + 64;
    const float* Bcol = B + cCol * BN + bCol;
    const float4 z4 = make_float4(0.f, 0.f, 0.f, 0.f);

    float4 a0, a1, b0, b1;

    // prologue: tile 0 -> buf 0
    a0 = (gr0 < M) ? *(const float4*)(A + (size_t)gr0 * K + aCol) : z4;
    a1 = (gr1 < M) ? *(const float4*)(A + (size_t)gr1 * K + aCol) : z4;
    b0 = *(const float4*)(Bcol + (size_t)bRow * Nc);
    b1 = *(const float4*)(Bcol + (size_t)(bRow + 8) * Nc);
    As[0][aCol + 0][aRow] = a0.x;  As[0][aCol + 1][aRow] = a0.y;
    As[0][aCol + 2][aRow] = a0.z;  As[0][aCol + 3][aRow] = a0.w;
    As[0][aCol + 0][aRow + 64] = a1.x;  As[0][aCol + 1][aRow + 64] = a1.y;
    As[0][aCol + 2][aRow + 64] = a1.z;  As[0][aCol + 3][aRow + 64] = a1.w;
    *(float4*)&Bs[0][bRow][bCol] = b0;
    *(float4*)&Bs[0][bRow + 8][bCol] = b1;
    __syncthreads();

    float acc[8][8];
#pragma unroll
    for (int i = 0; i < 8; i++)
#pragma unroll
        for (int j = 0; j < 8; j++) acc[i][j] = 0.f;

    float regM[8], regN[8];
    int T = K / BKK;

    for (int t = 0; t < T; t++) {
        int buf = t & 1;
        if (t + 1 < T) {
            int k0 = (t + 1) * BKK;
            a0 = (gr0 < M) ? *(const float4*)(A + (size_t)gr0 * K + k0 + aCol) : z4;
            a1 = (gr1 < M) ? *(const float4*)(A + (size_t)gr1 * K + k0 + aCol) : z4;
            b0 = *(const float4*)(Bcol + (size_t)(k0 + bRow) * Nc);
            b1 = *(const float4*)(Bcol + (size_t)(k0 + bRow + 8) * Nc);
        }
#pragma unroll
        for (int kk = 0; kk < BKK; kk++) {
#pragma unroll
            for (int i = 0; i < 8; i++) regM[i] = As[buf][kk][tRow * 8 + i];
#pragma unroll
            for (int j = 0; j < 8; j++) regN[j] = Bs[buf][kk][tCol * 8 + j];
#pragma unroll
            for (int i = 0; i < 8; i++)
#pragma unroll
                for (int j = 0; j < 8; j++) acc[i][j] = fmaf(regM[i], regN[j], acc[i][j]);
        }
        if (t + 1 < T) {
            int nb = buf ^ 1;
            As[nb][aCol + 0][aRow] = a0.x;  As[nb][aCol + 1][aRow] = a0.y;
            As[nb][aCol + 2][aRow] = a0.z;  As[nb][aCol + 3][aRow] = a0.w;
            As[nb][aCol + 0][aRow + 64] = a1.x;  As[nb][aCol + 1][aRow + 64] = a1.y;
            As[nb][aCol + 2][aRow + 64] = a1.z;  As[nb][aCol + 3][aRow + 64] = a1.w;
            *(float4*)&Bs[nb][bRow][bCol] = b0;
            *(float4*)&Bs[nb][bRow + 8][bCol] = b1;
            __syncthreads();
        }
    }

#pragma unroll
    for (int i = 0; i < 8; i++) {
        int r = rowBase + tRow * 8 + i;
        if (r >= M) continue;
        float* Cr = C + (size_t)r * Nc + cCol * BN + tCol * 8;
        *(float4*)(Cr + 0) = make_float4(acc[i][0], acc[i][1], acc[i][2], acc[i][3]);
        *(float4*)(Cr + 4) = make_float4(acc[i][4], acc[i][5], acc[i][6], acc[i][7]);
    }
}

// ---------------- per-node attention logits -----------------------------------
__global__ void asad_kernel(const float* __restrict__ h,
                            const float* __restrict__ att_src,
                            const float* __restrict__ att_dst,
                            float4* __restrict__ as_out,
                            float4* __restrict__ ad_out) {
    int warp = (blockIdx.x * blockDim.x + threadIdx.x) >> 5;
    int lid = threadIdx.x & 31;
    if (warp >= NN) return;
    const float* hr = h + (size_t)warp * HC;
    float ps[4] = {0.f, 0.f, 0.f, 0.f};
    float pd[4] = {0.f, 0.f, 0.f, 0.f};
#pragma unroll
    for (int k = 0; k < 8; k++) {
        int c = lid + 32 * k;
        float v = hr[c];
        ps[k >> 1] = fmaf(v, att_src[c], ps[k >> 1]);
        pd[k >> 1] = fmaf(v, att_dst[c], pd[k >> 1]);
    }
#pragma unroll
    for (int off = 16; off; off >>= 1) {
#pragma unroll
        for (int hh = 0; hh < 4; hh++) {
            ps[hh] += __shfl_xor_sync(0xFFFFFFFFu, ps[hh], off);
            pd[hh] += __shfl_xor_sync(0xFFFFFFFFu, pd[hh], off);
        }
    }
    if (lid == 0) {
        as_out[warp] = make_float4(ps[0], ps[1], ps[2], ps[3]);
        ad_out[warp] = make_float4(pd[0], pd[1], pd[2], pd[3]);
    }
}

// ---------------- per-edge leaky-relu logits (written in CSR order) -----------
__global__ void edge_kernel(const int* __restrict__ srcsort,
                            const int* __restrict__ dstsort,
                            const float4* __restrict__ as_in,
                            const float4* __restrict__ ad_in,
                            float4* __restrict__ e_out) {
    int pos = blockIdx.x * blockDim.x + threadIdx.x;
    if (pos >= ET) return;
    int s = srcsort[pos];
    int d = dstsort[pos];
    float4 a = as_in[s];
    float4 b = ad_in[d];
    float4 e;
    float v;
    v = a.x + b.x; e.x = (v > 0.f) ? v : SLOPE * v;
    v = a.y + b.y; e.y = (v > 0.f) ? v : SLOPE * v;
    v = a.z + b.z; e.z = (v > 0.f) ? v : SLOPE * v;
    v = a.w + b.w; e.w = (v > 0.f) ? v : SLOPE * v;
    e_out[pos] = e;
}

// ---------------- node-centric softmax + aggregation + bias + relu + BN -------
__global__ __launch_bounds__(128) void agg_kernel(const int* __restrict__ srcsort,
                                                  const float* __restrict__ h,
                                                  const float4* __restrict__ esort,
                                                  const int* __restrict__ rowptr,
                                                  float* __restrict__ y,
                                                  const float* __restrict__ bias,
                                                  const float* __restrict__ gam,
                                                  const float* __restrict__ bet,
                                                  const float* __restrict__ rmean,
                                                  const float* __restrict__ rvar) {
    int warp = (blockIdx.x * blockDim.x + threadIdx.x) >> 5;
    int lid = threadIdx.x & 31;
    if (warp >= NN) return;
    int beg = rowptr[warp], end = rowptr[warp + 1];

    float m[4], s[4];
#pragma unroll
    for (int hh = 0; hh < 4; hh++) { m[hh] = -1e30f; s[hh] = 0.f; }

    for (int j = beg + lid; j < end; j += 32) {
        float4 e4 = esort[j];                       // contiguous
        float ev[4] = {e4.x, e4.y, e4.z, e4.w};
#pragma unroll
        for (int hh = 0; hh < 4; hh++) {
            float mn = fmaxf(m[hh], ev[hh]);
            s[hh] = s[hh] * __expf(m[hh] - mn) + __expf(ev[hh] - mn);
            m[hh] = mn;
        }
    }
#pragma unroll
    for (int off = 16; off; off >>= 1) {
#pragma unroll
        for (int hh = 0; hh < 4; hh++) {
            float mo = __shfl_xor_sync(0xFFFFFFFFu, m[hh], off);
            float so = __shfl_xor_sync(0xFFFFFFFFu, s[hh], off);
            float mn = fmaxf(m[hh], mo);
            s[hh] = s[hh] * __expf(m[hh] - mn) + so * __expf(mo - mn);
            m[hh] = mn;
        }
    }
    float inv[4];
#pragma unroll
    for (int hh = 0; hh < 4; hh++) inv[hh] = 1.f / s[hh];

    float acc[8] = {0.f, 0.f, 0.f, 0.f, 0.f, 0.f, 0.f, 0.f};
    for (int j = beg; j < end; j++) {
        int src = srcsort[j];                      // warp-uniform (broadcast)
        float4 e4 = esort[j];                      // warp-uniform
        float al[4] = {__expf(e4.x - m[0]) * inv[0], __expf(e4.y - m[1]) * inv[1],
                       __expf(e4.z - m[2]) * inv[2], __expf(e4.w - m[3]) * inv[3]};
        const float* hs = h + (size_t)src * HC;
#pragma unroll
        for (int k = 0; k < 8; k++)
            acc[k] = fmaf(hs[lid + 32 * k], al[k >> 1], acc[k]);
    }

    size_t ob = (size_t)warp * HC;
#pragma unroll
    for (int k = 0; k < 8; k++) {
        int c = lid + 32 * k;
        float v = acc[k] + bias[c];
        v = fmaxf(v, 0.f);
        v = (v - rmean[c]) * rsqrtf(rvar[c] + BNEPS) * gam[c] + bet[c];
        y[ob + c] = v;
    }
}

// ---------------- pooling ------------------------------------------------------
__device__ __forceinline__ int lowerb(const int* b, int n, int key) {
    int lo = 0, hi = n;
    while (lo < hi) {
        int mid = (lo + hi) >> 1;
        if (b[mid] < key) lo = mid + 1; else hi = mid;
    }
    return lo;
}

__global__ void pool_kernel(const int* __restrict__ batch,
                            const float* __restrict__ y,
                            float* __restrict__ pooled) {
    int g = blockIdx.x;
    int c = threadIdx.x;     // 256
    __shared__ int s_lo, s_hi;
    if (c == 0) {
        s_lo = lowerb(batch, NN, g);
        s_hi = lowerb(batch, NN, g + 1);
    }
    __syncthreads();
    float sum = 0.f;
    for (int n = s_lo; n < s_hi; n++) sum += y[(size_t)n * HC + c];
    int cnt = s_hi - s_lo;
    float denom = (cnt > 0) ? (float)cnt : 1.f;
    pooled[g * HC + c] = sum / denom;
}

// ---------------- MLP head -----------------------------------------------------
__global__ void head_kernel(const float* __restrict__ pooled,
                            const float* __restrict__ lw1, const float* __restrict__ lb1,
                            const float* __restrict__ lw2, const float* __restrict__ lb2,
                            float* __restrict__ out) {
    int g = blockIdx.x;
    int j = threadIdx.x;     // 128
    __shared__ float sp[256];
    __shared__ float r0[128], r1[128];
    sp[j] = pooled[g * HC + j];
    sp[j + 128] = pooled[g * HC + 128 + j];
    __syncthreads();
    float z = lb1[j];
#pragma unroll 4
    for (int k = 0; k < 256; k++) z = fmaf(sp[k], lw1[k * 128 + j], z);
    z = fmaxf(z, 0.f);
    r0[j] = z * lw2[j * 2 + 0];
    r1[j] = z * lw2[j * 2 + 1];
    __syncthreads();
    for (int off = 64; off; off >>= 1) {
        if (j < off) { r0[j] += r0[j + off]; r1[j] += r1[j + off]; }
        __syncthreads();
    }
    if (j == 0) {
        out[g * 2 + 0] = r0[0] + lb2[0];
        out[g * 2 + 1] = r1[0] + lb2[1];
    }
}

// ---------------- launcher ------------------------------------------------------
extern "C" void kernel_launch(void* const* d_in, const int* in_sizes, int n_in,
                              void* d_out, int out_size) {
    const float* x        = (const float*)d_in[0];
    const void*  ei       = d_in[1];
    const void*  batchraw = d_in[2];
    const float* W1       = (const float*)d_in[3];
    const float* att_src1 = (const float*)d_in[4];
    const float* att_dst1 = (const float*)d_in[5];
    const float* b1       = (const float*)d_in[6];
    const float* g1       = (const float*)d_in[7];
    const float* be1      = (const float*)d_in[8];
    const float* rm1      = (const float*)d_in[9];
    const float* rv1      = (const float*)d_in[10];
    const float* W2       = (const float*)d_in[11];
    const float* att_src2 = (const float*)d_in[12];
    const float* att_dst2 = (const float*)d_in[13];
    const float* b2       = (const float*)d_in[14];
    const float* g2       = (const float*)d_in[15];
    const float* be2      = (const float*)d_in[16];
    const float* rm2      = (const float*)d_in[17];
    const float* rv2      = (const float*)d_in[18];
    const float* lw1      = (const float*)d_in[19];
    const float* lb1      = (const float*)d_in[20];
    const float* lw2      = (const float*)d_in[21];
    const float* lb2      = (const float*)d_in[22];

    float*  p_h = nullptr;  float*  p_y = nullptr;  float4* p_as = nullptr;
    float4* p_ad = nullptr; float4* p_esort = nullptr; int* p_deg = nullptr;
    int* p_rowptr = nullptr; int* p_cursor = nullptr;
    int* p_srcsort = nullptr; int* p_dstsort = nullptr;
    float* p_pooled = nullptr; int* p_src = nullptr; int* p_dst = nullptr;
    int* p_batch = nullptr; int* p_is64 = nullptr;
    cudaGetSymbolAddress((void**)&p_h, g_h);
    cudaGetSymbolAddress((void**)&p_y, g_y);
    cudaGetSymbolAddress((void**)&p_as, g_as);
    cudaGetSymbolAddress((void**)&p_ad, g_ad);
    cudaGetSymbolAddress((void**)&p_esort, g_esort);
    cudaGetSymbolAddress((void**)&p_deg, g_deg);
    cudaGetSymbolAddress((void**)&p_rowptr, g_rowptr);
    cudaGetSymbolAddress((void**)&p_cursor, g_cursor);
    cudaGetSymbolAddress((void**)&p_srcsort, g_srcsort);
    cudaGetSymbolAddress((void**)&p_dstsort, g_dstsort);
    cudaGetSymbolAddress((void**)&p_pooled, g_pooled);
    cudaGetSymbolAddress((void**)&p_src, g_src);
    cudaGetSymbolAddress((void**)&p_dst, g_dst);
    cudaGetSymbolAddress((void**)&p_batch, g_batch);
    cudaGetSymbolAddress((void**)&p_is64, g_is64);

    dim3 ggrid(HC / BN, (NN + BM - 1) / BM);
    int aggBlocks = (NN * 32 + 127) / 128;
    int warpBlocks = (NN * 32 + 255) / 256;

    // (1) dtype detect  (2) prep  (3) count  (4) sgemm1 <- ncu capture slot
    detect_kernel<<<1, 1024>>>((const unsigned*)ei, p_is64);
    prep_kernel<<<(EE + 255) / 256, 256>>>(ei, batchraw, p_is64, p_src, p_dst,
                                           p_batch, p_deg);
    count_kernel<<<(ET + 255) / 256, 256>>>(p_dst, p_deg);
    sgemm_kernel<<<ggrid, 256>>>(x, W1, p_h, NN, FIN);

    // finish CSR build (independent of sgemm1)
    scan_kernel<<<1, 1024>>>(p_deg, p_rowptr, p_cursor);
    fill_kernel<<<(ET + 255) / 256, 256>>>(p_src, p_dst, p_cursor, p_srcsort, p_dstsort);

    // ---- layer 1 ----
    asad_kernel<<<warpBlocks, 256>>>(p_h, att_src1, att_dst1, p_as, p_ad);
    edge_kernel<<<(ET + 255) / 256, 256>>>(p_srcsort, p_dstsort, p_as, p_ad, p_esort);
    agg_kernel<<<aggBlocks, 128>>>(p_srcsort, p_h, p_esort, p_rowptr, p_y,
                                   b1, g1, be1, rm1, rv1);

    // ---- layer 2 ----
    sgemm_kernel<<<ggrid, 256>>>(p_y, W2, p_h, NN, HC);
    asad_kernel<<<warpBlocks, 256>>>(p_h, att_src2, att_dst2, p_as, p_ad);
    edge_kernel<<<(ET + 255) / 256, 256>>>(p_srcsort, p_dstsort, p_as, p_ad, p_esort);
    agg_kernel<<<aggBlocks, 128>>>(p_srcsort, p_h, p_esort, p_rowptr, p_y,
                                   b2, g2, be2, rm2, rv2);

    // ---- pool + head ----
    pool_kernel<<<NG, 256>>>(p_batch, p_y, p_pooled);
    head_kernel<<<NG, 128>>>(p_pooled, lw1, lb1, lw2, lb2, (float*)d_out);
}

// round 6
// speedup vs baseline: 1.5173x; 1.4054x over previous
#include <cuda_runtime.h>
#include <cuda_bf16.h>
#include <math.h>

#define NN 50000
#define EE 800000
#define ET 850000      // EE + NN self loops
#define FIN 128
#define HC 256         // HEADS*HID
#define NG 500
#define SLOPE 0.2f
#define BNEPS 1e-5f

// ---------------- scratch (device globals; no runtime allocation) -------------
__device__ __align__(256) float  g_h[(size_t)NN * HC];   // GEMM output
__device__ __align__(256) float  g_y[(size_t)NN * HC];   // layer output
__device__ float4 g_as[NN];
__device__ float4 g_ad[NN];
__device__ float4 g_esort[ET];     // edge logits in CSR order
__device__ int    g_srcsort[ET];   // src node per CSR slot
__device__ int    g_dstsort[ET];   // dst node per CSR slot
__device__ int    g_deg[NN];
__device__ int    g_rowptr[NN + 1];
__device__ int    g_cursor[NN];
__device__ __align__(256) float  g_pooled[NG * HC];
__device__ int    g_src[EE];
__device__ int    g_dst[EE];
__device__ int    g_batch[NN];
__device__ int    g_is64;

// ---------------- dtype detect ------------------------------------------------
__global__ void detect_kernel(const unsigned* __restrict__ eiw, int* __restrict__ is64) {
    __shared__ int s_any;
    if (threadIdx.x == 0) s_any = 0;
    __syncthreads();
    unsigned v = eiw[threadIdx.x * 2 + 1];
    if (v != 0u) atomicOr(&s_any, 1);
    __syncthreads();
    if (threadIdx.x == 0) *is64 = s_any ? 0 : 1;
}

// ---------------- combined prep -------------------------------------------------
__global__ void prep_kernel(const void* __restrict__ ei, const void* __restrict__ b,
                            const int* __restrict__ is64,
                            int* __restrict__ src, int* __restrict__ dst,
                            int* __restrict__ batch, int* __restrict__ deg) {
    int i = blockIdx.x * blockDim.x + threadIdx.x;
    int w = *is64;
    if (i < EE) {
        if (w) {
            const long long* p = (const long long*)ei;
            src[i] = (int)p[i];
            dst[i] = (int)p[EE + i];
        } else {
            const int* p = (const int*)ei;
            src[i] = p[i];
            dst[i] = p[EE + i];
        }
    }
    if (i < NN) {
        batch[i] = w ? (int)((const long long*)b)[i] : ((const int*)b)[i];
        deg[i] = 0;
    }
}

// ---------------- CSR build ---------------------------------------------------
__global__ void count_kernel(const int* __restrict__ edst, int* __restrict__ deg) {
    int eid = blockIdx.x * blockDim.x + threadIdx.x;
    if (eid >= ET) return;
    int d = (eid < EE) ? edst[eid] : (eid - EE);
    atomicAdd(&deg[d], 1);
}

__global__ void scan_kernel(const int* __restrict__ deg, int* __restrict__ rowptr,
                            int* __restrict__ cursor) {
    __shared__ int sdata[1024];
    __shared__ int s_carry;
    int tid = threadIdx.x;
    if (tid == 0) s_carry = 0;
    __syncthreads();
    for (int base = 0; base < NN; base += 1024) {
        int i = base + tid;
        int v = (i < NN) ? deg[i] : 0;
        sdata[tid] = v;
        __syncthreads();
        for (int off = 1; off < 1024; off <<= 1) {
            int t = (tid >= off) ? sdata[tid - off] : 0;
            __syncthreads();
            sdata[tid] += t;
            __syncthreads();
        }
        if (i < NN) {
            rowptr[i + 1] = sdata[tid] + s_carry;
            cursor[i] = sdata[tid] + s_carry - v;
        }
        __syncthreads();
        if (tid == 0) s_carry += sdata[1023];
        __syncthreads();
    }
    if (tid == 0) rowptr[0] = 0;
}

__global__ void fill_kernel(const int* __restrict__ esrc, const int* __restrict__ edst,
                            int* __restrict__ cursor,
                            int* __restrict__ srcsort, int* __restrict__ dstsort) {
    int eid = blockIdx.x * blockDim.x + threadIdx.x;
    if (eid >= ET) return;
    int s, d;
    if (eid < EE) { s = esrc[eid]; d = edst[eid]; }
    else          { s = eid - EE; d = s; }
    int pos = atomicAdd(&cursor[d], 1);
    srcsort[pos] = s;
    dstsort[pos] = d;
}

// ---------------- TF32 tensor-core GEMM: C = A[M,K] @ B[K,256] -----------------
// 128x128 block, 8 warps x (32M x 64N), BK=16 double-buffered, mma.m16n8k8.tf32
#define BM 128
#define BN 128
#define SMS 136    // smem row stride (bank-conflict-free fragment loads)

__device__ __forceinline__ float f2tf(float x) {
    unsigned u;
    asm("cvt.rna.tf32.f32 %0, %1;" : "=r"(u) : "f"(x));
    return __uint_as_float(u);
}

__global__ __launch_bounds__(256) void tgemm_kernel(const float* __restrict__ A,
                                                    const float* __restrict__ B,
                                                    float* __restrict__ C,
                                                    int M, int K) {
    __shared__ float As[2][16][SMS];
    __shared__ float Bs[2][16][SMS];
    const int Nc = HC;

    int tid = threadIdx.x;
    int warp = tid >> 5, lane = tid & 31;
    int warpM = (warp & 3) * 32;
    int warpN = (warp >> 2) * 64;
    int cRow = blockIdx.y, cCol = blockIdx.x;
    int rowBase = cRow * BM;

    int aRow = tid >> 2;            // 0..63
    int aCol = (tid & 3) << 2;      // 0,4,8,12
    int bRow = tid >> 5;            // 0..7
    int bCol = (tid & 31) << 2;     // 0..124
    int gr0 = rowBase + aRow;
    int gr1 = gr0 + 64;
    const float* Bcol = B + cCol * BN + bCol;
    const float4 z4 = make_float4(0.f, 0.f, 0.f, 0.f);

    float4 a0, a1, b0, b1;

    // prologue -> buf 0
    a0 = (gr0 < M) ? *(const float4*)(A + (size_t)gr0 * K + aCol) : z4;
    a1 = (gr1 < M) ? *(const float4*)(A + (size_t)gr1 * K + aCol) : z4;
    b0 = *(const float4*)(Bcol + (size_t)bRow * Nc);
    b1 = *(const float4*)(Bcol + (size_t)(bRow + 8) * Nc);
    As[0][aCol + 0][aRow] = f2tf(a0.x);  As[0][aCol + 1][aRow] = f2tf(a0.y);
    As[0][aCol + 2][aRow] = f2tf(a0.z);  As[0][aCol + 3][aRow] = f2tf(a0.w);
    As[0][aCol + 0][aRow + 64] = f2tf(a1.x);  As[0][aCol + 1][aRow + 64] = f2tf(a1.y);
    As[0][aCol + 2][aRow + 64] = f2tf(a1.z);  As[0][aCol + 3][aRow + 64] = f2tf(a1.w);
    Bs[0][bRow][bCol + 0] = f2tf(b0.x);  Bs[0][bRow][bCol + 1] = f2tf(b0.y);
    Bs[0][bRow][bCol + 2] = f2tf(b0.z);  Bs[0][bRow][bCol + 3] = f2tf(b0.w);
    Bs[0][bRow + 8][bCol + 0] = f2tf(b1.x);  Bs[0][bRow + 8][bCol + 1] = f2tf(b1.y);
    Bs[0][bRow + 8][bCol + 2] = f2tf(b1.z);  Bs[0][bRow + 8][bCol + 3] = f2tf(b1.w);
    __syncthreads();

    float d[2][8][4];
#pragma unroll
    for (int i = 0; i < 2; i++)
#pragma unroll
        for (int j = 0; j < 8; j++)
#pragma unroll
            for (int q = 0; q < 4; q++) d[i][j][q] = 0.f;

    int T = K / 16;
    int lr = lane >> 2;     // 0..7
    int lc = lane & 3;      // 0..3

    for (int t = 0; t < T; t++) {
        int buf = t & 1;
        if (t + 1 < T) {
            int k0 = (t + 1) * 16;
            a0 = (gr0 < M) ? *(const float4*)(A + (size_t)gr0 * K + k0 + aCol) : z4;
            a1 = (gr1 < M) ? *(const float4*)(A + (size_t)gr1 * K + k0 + aCol) : z4;
            b0 = *(const float4*)(Bcol + (size_t)(k0 + bRow) * Nc);
            b1 = *(const float4*)(Bcol + (size_t)(k0 + bRow + 8) * Nc);
        }
#pragma unroll
        for (int ks = 0; ks < 16; ks += 8) {
            unsigned af[2][4], bf[8][2];
#pragma unroll
            for (int mt = 0; mt < 2; mt++) {
                int r = warpM + 16 * mt + lr;
                af[mt][0] = __float_as_uint(As[buf][ks + lc][r]);
                af[mt][1] = __float_as_uint(As[buf][ks + lc][r + 8]);
                af[mt][2] = __float_as_uint(As[buf][ks + 4 + lc][r]);
                af[mt][3] = __float_as_uint(As[buf][ks + 4 + lc][r + 8]);
            }
#pragma unroll
            for (int nt = 0; nt < 8; nt++) {
                int c = warpN + 8 * nt + lr;
                bf[nt][0] = __float_as_uint(Bs[buf][ks + lc][c]);
                bf[nt][1] = __float_as_uint(Bs[buf][ks + 4 + lc][c]);
            }
#pragma unroll
            for (int mt = 0; mt < 2; mt++)
#pragma unroll
                for (int nt = 0; nt < 8; nt++) {
                    asm volatile(
                        "mma.sync.aligned.m16n8k8.row.col.f32.tf32.tf32.f32 "
                        "{%0,%1,%2,%3}, {%4,%5,%6,%7}, {%8,%9}, {%0,%1,%2,%3};"
                        : "+f"(d[mt][nt][0]), "+f"(d[mt][nt][1]),
                          "+f"(d[mt][nt][2]), "+f"(d[mt][nt][3])
                        : "r"(af[mt][0]), "r"(af[mt][1]), "r"(af[mt][2]), "r"(af[mt][3]),
                          "r"(bf[nt][0]), "r"(bf[nt][1]));
                }
        }
        if (t + 1 < T) {
            int nb = buf ^ 1;
            As[nb][aCol + 0][aRow] = f2tf(a0.x);  As[nb][aCol + 1][aRow] = f2tf(a0.y);
            As[nb][aCol + 2][aRow] = f2tf(a0.z);  As[nb][aCol + 3][aRow] = f2tf(a0.w);
            As[nb][aCol + 0][aRow + 64] = f2tf(a1.x);  As[nb][aCol + 1][aRow + 64] = f2tf(a1.y);
            As[nb][aCol + 2][aRow + 64] = f2tf(a1.z);  As[nb][aCol + 3][aRow + 64] = f2tf(a1.w);
            Bs[nb][bRow][bCol + 0] = f2tf(b0.x);  Bs[nb][bRow][bCol + 1] = f2tf(b0.y);
            Bs[nb][bRow][bCol + 2] = f2tf(b0.z);  Bs[nb][bRow][bCol + 3] = f2tf(b0.w);
            Bs[nb][bRow + 8][bCol + 0] = f2tf(b1.x);  Bs[nb][bRow + 8][bCol + 1] = f2tf(b1.y);
            Bs[nb][bRow + 8][bCol + 2] = f2tf(b1.z);  Bs[nb][bRow + 8][bCol + 3] = f2tf(b1.w);
            __syncthreads();
        }
    }

    // epilogue
#pragma unroll
    for (int mt = 0; mt < 2; mt++) {
        int r0 = rowBase + warpM + 16 * mt + lr;
        int r1 = r0 + 8;
#pragma unroll
        for (int nt = 0; nt < 8; nt++) {
            int c = cCol * BN + warpN + 8 * nt + 2 * lc;
            if (r0 < M)
                *(float2*)(C + (size_t)r0 * Nc + c) = make_float2(d[mt][nt][0], d[mt][nt][1]);
            if (r1 < M)
                *(float2*)(C + (size_t)r1 * Nc + c) = make_float2(d[mt][nt][2], d[mt][nt][3]);
        }
    }
}

// ---------------- per-node attention logits -----------------------------------
__global__ void asad_kernel(const float* __restrict__ h,
                            const float* __restrict__ att_src,
                            const float* __restrict__ att_dst,
                            float4* __restrict__ as_out,
                            float4* __restrict__ ad_out) {
    int warp = (blockIdx.x * blockDim.x + threadIdx.x) >> 5;
    int lid = threadIdx.x & 31;
    if (warp >= NN) return;
    const float* hr = h + (size_t)warp * HC;
    float ps[4] = {0.f, 0.f, 0.f, 0.f};
    float pd[4] = {0.f, 0.f, 0.f, 0.f};
#pragma unroll
    for (int k = 0; k < 8; k++) {
        int c = lid + 32 * k;
        float v = hr[c];
        ps[k >> 1] = fmaf(v, att_src[c], ps[k >> 1]);
        pd[k >> 1] = fmaf(v, att_dst[c], pd[k >> 1]);
    }
#pragma unroll
    for (int off = 16; off; off >>= 1) {
#pragma unroll
        for (int hh = 0; hh < 4; hh++) {
            ps[hh] += __shfl_xor_sync(0xFFFFFFFFu, ps[hh], off);
            pd[hh] += __shfl_xor_sync(0xFFFFFFFFu, pd[hh], off);
        }
    }
    if (lid == 0) {
        as_out[warp] = make_float4(ps[0], ps[1], ps[2], ps[3]);
        ad_out[warp] = make_float4(pd[0], pd[1], pd[2], pd[3]);
    }
}

// ---------------- per-edge leaky-relu logits (CSR order) ----------------------
__global__ void edge_kernel(const int* __restrict__ srcsort,
                            const int* __restrict__ dstsort,
                            const float4* __restrict__ as_in,
                            const float4* __restrict__ ad_in,
                            float4* __restrict__ e_out) {
    int pos = blockIdx.x * blockDim.x + threadIdx.x;
    if (pos >= ET) return;
    int s = srcsort[pos];
    int d = dstsort[pos];
    float4 a = as_in[s];
    float4 b = ad_in[d];
    float4 e;
    float v;
    v = a.x + b.x; e.x = (v > 0.f) ? v : SLOPE * v;
    v = a.y + b.y; e.y = (v > 0.f) ? v : SLOPE * v;
    v = a.z + b.z; e.z = (v > 0.f) ? v : SLOPE * v;
    v = a.w + b.w; e.w = (v > 0.f) ? v : SLOPE * v;
    e_out[pos] = e;
}

// ---------------- node-centric softmax + aggregation + bias + relu + BN -------
__global__ __launch_bounds__(128) void agg_kernel(const int* __restrict__ srcsort,
                                                  const float* __restrict__ h,
                                                  const float4* __restrict__ esort,
                                                  const int* __restrict__ rowptr,
                                                  float* __restrict__ y,
                                                  const float* __restrict__ bias,
                                                  const float* __restrict__ gam,
                                                  const float* __restrict__ bet,
                                                  const float* __restrict__ rmean,
                                                  const float* __restrict__ rvar) {
    int warp = (blockIdx.x * blockDim.x + threadIdx.x) >> 5;
    int lid = threadIdx.x & 31;
    if (warp >= NN) return;
    int beg = rowptr[warp], end = rowptr[warp + 1];

    float m[4], s[4];
#pragma unroll
    for (int hh = 0; hh < 4; hh++) { m[hh] = -1e30f; s[hh] = 0.f; }

    for (int j = beg + lid; j < end; j += 32) {
        float4 e4 = esort[j];
        float ev[4] = {e4.x, e4.y, e4.z, e4.w};
#pragma unroll
        for (int hh = 0; hh < 4; hh++) {
            float mn = fmaxf(m[hh], ev[hh]);
            s[hh] = s[hh] * __expf(m[hh] - mn) + __expf(ev[hh] - mn);
            m[hh] = mn;
        }
    }
#pragma unroll
    for (int off = 16; off; off >>= 1) {
#pragma unroll
        for (int hh = 0; hh < 4; hh++) {
            float mo = __shfl_xor_sync(0xFFFFFFFFu, m[hh], off);
            float so = __shfl_xor_sync(0xFFFFFFFFu, s[hh], off);
            float mn = fmaxf(m[hh], mo);
            s[hh] = s[hh] * __expf(m[hh] - mn) + so * __expf(mo - mn);
            m[hh] = mn;
        }
    }
    float inv[4];
#pragma unroll
    for (int hh = 0; hh < 4; hh++) inv[hh] = 1.f / s[hh];

    float acc[8] = {0.f, 0.f, 0.f, 0.f, 0.f, 0.f, 0.f, 0.f};
    for (int j = beg; j < end; j++) {
        int src = srcsort[j];
        float4 e4 = esort[j];
        float al[4] = {__expf(e4.x - m[0]) * inv[0], __expf(e4.y - m[1]) * inv[1],
                       __expf(e4.z - m[2]) * inv[2], __expf(e4.w - m[3]) * inv[3]};
        const float* hs = h + (size_t)src * HC;
#pragma unroll
        for (int k = 0; k < 8; k++)
            acc[k] = fmaf(hs[lid + 32 * k], al[k >> 1], acc[k]);
    }

    size_t ob = (size_t)warp * HC;
#pragma unroll
    for (int k = 0; k < 8; k++) {
        int c = lid + 32 * k;
        float v = acc[k] + bias[c];
        v = fmaxf(v, 0.f);
        v = (v - rmean[c]) * rsqrtf(rvar[c] + BNEPS) * gam[c] + bet[c];
        y[ob + c] = v;
    }
}

// ---------------- pooling ------------------------------------------------------
__device__ __forceinline__ int lowerb(const int* b, int n, int key) {
    int lo = 0, hi = n;
    while (lo < hi) {
        int mid = (lo + hi) >> 1;
        if (b[mid] < key) lo = mid + 1; else hi = mid;
    }
    return lo;
}

__global__ void pool_kernel(const int* __restrict__ batch,
                            const float* __restrict__ y,
                            float* __restrict__ pooled) {
    int g = blockIdx.x;
    int c = threadIdx.x;
    __shared__ int s_lo, s_hi;
    if (c == 0) {
        s_lo = lowerb(batch, NN, g);
        s_hi = lowerb(batch, NN, g + 1);
    }
    __syncthreads();
    float sum = 0.f;
    for (int n = s_lo; n < s_hi; n++) sum += y[(size_t)n * HC + c];
    int cnt = s_hi - s_lo;
    float denom = (cnt > 0) ? (float)cnt : 1.f;
    pooled[g * HC + c] = sum / denom;
}

// ---------------- MLP head -----------------------------------------------------
__global__ void head_kernel(const float* __restrict__ pooled,
                            const float* __restrict__ lw1, const float* __restrict__ lb1,
                            const float* __restrict__ lw2, const float* __restrict__ lb2,
                            float* __restrict__ out) {
    int g = blockIdx.x;
    int j = threadIdx.x;
    __shared__ float sp[256];
    __shared__ float r0[128], r1[128];
    sp[j] = pooled[g * HC + j];
    sp[j + 128] = pooled[g * HC + 128 + j];
    __syncthreads();
    float z = lb1[j];
#pragma unroll 4
    for (int k = 0; k < 256; k++) z = fmaf(sp[k], lw1[k * 128 + j], z);
    z = fmaxf(z, 0.f);
    r0[j] = z * lw2[j * 2 + 0];
    r1[j] = z * lw2[j * 2 + 1];
    __syncthreads();
    for (int off = 64; off; off >>= 1) {
        if (j < off) { r0[j] += r0[j + off]; r1[j] += r1[j + off]; }
        __syncthreads();
    }
    if (j == 0) {
        out[g * 2 + 0] = r0[0] + lb2[0];
        out[g * 2 + 1] = r1[0] + lb2[1];
    }
}

// ---------------- launcher ------------------------------------------------------
extern "C" void kernel_launch(void* const* d_in, const int* in_sizes, int n_in,
                              void* d_out, int out_size) {
    const float* x        = (const float*)d_in[0];
    const void*  ei       = d_in[1];
    const void*  batchraw = d_in[2];
    const float* W1       = (const float*)d_in[3];
    const float* att_src1 = (const float*)d_in[4];
    const float* att_dst1 = (const float*)d_in[5];
    const float* b1       = (const float*)d_in[6];
    const float* g1       = (const float*)d_in[7];
    const float* be1      = (const float*)d_in[8];
    const float* rm1      = (const float*)d_in[9];
    const float* rv1      = (const float*)d_in[10];
    const float* W2       = (const float*)d_in[11];
    const float* att_src2 = (const float*)d_in[12];
    const float* att_dst2 = (const float*)d_in[13];
    const float* b2       = (const float*)d_in[14];
    const float* g2       = (const float*)d_in[15];
    const float* be2      = (const float*)d_in[16];
    const float* rm2      = (const float*)d_in[17];
    const float* rv2      = (const float*)d_in[18];
    const float* lw1      = (const float*)d_in[19];
    const float* lb1      = (const float*)d_in[20];
    const float* lw2      = (const float*)d_in[21];
    const float* lb2      = (const float*)d_in[22];

    float*  p_h = nullptr;  float*  p_y = nullptr;  float4* p_as = nullptr;
    float4* p_ad = nullptr; float4* p_esort = nullptr; int* p_deg = nullptr;
    int* p_rowptr = nullptr; int* p_cursor = nullptr;
    int* p_srcsort = nullptr; int* p_dstsort = nullptr;
    float* p_pooled = nullptr; int* p_src = nullptr; int* p_dst = nullptr;
    int* p_batch = nullptr; int* p_is64 = nullptr;
    cudaGetSymbolAddress((void**)&p_h, g_h);
    cudaGetSymbolAddress((void**)&p_y, g_y);
    cudaGetSymbolAddress((void**)&p_as, g_as);
    cudaGetSymbolAddress((void**)&p_ad, g_ad);
    cudaGetSymbolAddress((void**)&p_esort, g_esort);
    cudaGetSymbolAddress((void**)&p_deg, g_deg);
    cudaGetSymbolAddress((void**)&p_rowptr, g_rowptr);
    cudaGetSymbolAddress((void**)&p_cursor, g_cursor);
    cudaGetSymbolAddress((void**)&p_srcsort, g_srcsort);
    cudaGetSymbolAddress((void**)&p_dstsort, g_dstsort);
    cudaGetSymbolAddress((void**)&p_pooled, g_pooled);
    cudaGetSymbolAddress((void**)&p_src, g_src);
    cudaGetSymbolAddress((void**)&p_dst, g_dst);
    cudaGetSymbolAddress((void**)&p_batch, g_batch);
    cudaGetSymbolAddress((void**)&p_is64, g_is64);

    dim3 ggrid(HC / BN, (NN + BM - 1) / BM);
    int aggBlocks = (NN * 32 + 127) / 128;
    int warpBlocks = (NN * 32 + 255) / 256;

    // (1) detect (2) prep (3) count (4) tgemm1 <- ncu capture slot
    detect_kernel<<<1, 1024>>>((const unsigned*)ei, p_is64);
    prep_kernel<<<(EE + 255) / 256, 256>>>(ei, batchraw, p_is64, p_src, p_dst,
                                           p_batch, p_deg);
    count_kernel<<<(ET + 255) / 256, 256>>>(p_dst, p_deg);
    tgemm_kernel<<<ggrid, 256>>>(x, W1, p_h, NN, FIN);

    scan_kernel<<<1, 1024>>>(p_deg, p_rowptr, p_cursor);
    fill_kernel<<<(ET + 255) / 256, 256>>>(p_src, p_dst, p_cursor, p_srcsort, p_dstsort);

    // ---- layer 1 ----
    asad_kernel<<<warpBlocks, 256>>>(p_h, att_src1, att_dst1, p_as, p_ad);
    edge_kernel<<<(ET + 255) / 256, 256>>>(p_srcsort, p_dstsort, p_as, p_ad, p_esort);
    agg_kernel<<<aggBlocks, 128>>>(p_srcsort, p_h, p_esort, p_rowptr, p_y,
                                   b1, g1, be1, rm1, rv1);

    // ---- layer 2 ----
    tgemm_kernel<<<ggrid, 256>>>(p_y, W2, p_h, NN, HC);
    asad_kernel<<<warpBlocks, 256>>>(p_h, att_src2, att_dst2, p_as, p_ad);
    edge_kernel<<<(ET + 255) / 256, 256>>>(p_srcsort, p_dstsort, p_as, p_ad, p_esort);
    agg_kernel<<<aggBlocks, 128>>>(p_srcsort, p_h, p_esort, p_rowptr, p_y,
                                   b2, g2, be2, rm2, rv2);

    // ---- pool + head ----
    pool_kernel<<<NG, 256>>>(p_batch, p_y, p_pooled);
    head_kernel<<<NG, 128>>>(p_pooled, lw1, lb1, lw2, lb2, (float*)d_out);
}

// round 7
// speedup vs baseline: 1.7539x; 1.1560x over previous
#include <cuda_runtime.h>
#include <cuda_bf16.h>
#include <math.h>

#define NN 50000
#define EE 800000
#define ET 850000      // EE + NN self loops
#define FIN 128
#define HC 256         // HEADS*HID
#define NG 500
#define SLOPE 0.2f
#define BNEPS 1e-5f

// ---------------- scratch (device globals; no runtime allocation) -------------
__device__ __align__(256) float  g_h[(size_t)NN * HC];   // GEMM output
__device__ __align__(256) float  g_y[(size_t)NN * HC];   // layer output
__device__ float4 g_as[NN];
__device__ float4 g_ad[NN];
__device__ int    g_srcsort[ET];   // src node per CSR slot
__device__ int    g_deg[NN];
__device__ int    g_rowptr[NN + 1];
__device__ int    g_cursor[NN];
__device__ __align__(256) float  g_pooled[NG * HC];
__device__ int    g_src[EE];
__device__ int    g_dst[EE];
__device__ int    g_batch[NN];
__device__ int    g_is64;
#define SCAN_B 256
#define NB ((NN + SCAN_B - 1) / SCAN_B)    // 196
__device__ int    g_bsum[NB];
__device__ int    g_boff[NB];

// ---------------- dtype detect ------------------------------------------------
__global__ void detect_kernel(const unsigned* __restrict__ eiw, int* __restrict__ is64) {
    __shared__ int s_any;
    if (threadIdx.x == 0) s_any = 0;
    __syncthreads();
    unsigned v = eiw[threadIdx.x * 2 + 1];
    if (v != 0u) atomicOr(&s_any, 1);
    __syncthreads();
    if (threadIdx.x == 0) *is64 = s_any ? 0 : 1;
}

// ---------------- combined prep -------------------------------------------------
__global__ void prep_kernel(const void* __restrict__ ei, const void* __restrict__ b,
                            const int* __restrict__ is64,
                            int* __restrict__ src, int* __restrict__ dst,
                            int* __restrict__ batch, int* __restrict__ deg) {
    int i = blockIdx.x * blockDim.x + threadIdx.x;
    int w = *is64;
    if (i < EE) {
        if (w) {
            const long long* p = (const long long*)ei;
            src[i] = (int)p[i];
            dst[i] = (int)p[EE + i];
        } else {
            const int* p = (const int*)ei;
            src[i] = p[i];
            dst[i] = p[EE + i];
        }
    }
    if (i < NN) {
        batch[i] = w ? (int)((const long long*)b)[i] : ((const int*)b)[i];
        deg[i] = 0;
    }
}

// ---------------- CSR build ---------------------------------------------------
__global__ void count_kernel(const int* __restrict__ edst, int* __restrict__ deg) {
    int eid = blockIdx.x * blockDim.x + threadIdx.x;
    if (eid >= ET) return;
    int d = (eid < EE) ? edst[eid] : (eid - EE);
    atomicAdd(&deg[d], 1);
}

// hierarchical scan: block sums -> scan block sums -> per-block scatter
__global__ void blocksum_kernel(const int* __restrict__ deg, int* __restrict__ bsum) {
    __shared__ int sd[SCAN_B];
    int tid = threadIdx.x;
    int i = blockIdx.x * SCAN_B + tid;
    sd[tid] = (i < NN) ? deg[i] : 0;
    __syncthreads();
    for (int off = SCAN_B / 2; off; off >>= 1) {
        if (tid < off) sd[tid] += sd[tid + off];
        __syncthreads();
    }
    if (tid == 0) bsum[blockIdx.x] = sd[0];
}

__global__ void scanb_kernel(const int* __restrict__ bsum, int* __restrict__ boff) {
    __shared__ int sd[256];
    int tid = threadIdx.x;
    int v = (tid < NB) ? bsum[tid] : 0;
    sd[tid] = v;
    __syncthreads();
    for (int off = 1; off < 256; off <<= 1) {
        int t = (tid >= off) ? sd[tid - off] : 0;
        __syncthreads();
        sd[tid] += t;
        __syncthreads();
    }
    if (tid < NB) boff[tid] = sd[tid] - v;     // exclusive
}

__global__ void scatter_kernel(const int* __restrict__ deg, const int* __restrict__ boff,
                               int* __restrict__ rowptr, int* __restrict__ cursor) {
    __shared__ int sd[SCAN_B];
    int tid = threadIdx.x;
    int i = blockIdx.x * SCAN_B + tid;
    int v = (i < NN) ? deg[i] : 0;
    sd[tid] = v;
    __syncthreads();
    for (int off = 1; off < SCAN_B; off <<= 1) {
        int t = (tid >= off) ? sd[tid - off] : 0;
        __syncthreads();
        sd[tid] += t;
        __syncthreads();
    }
    int base = boff[blockIdx.x];
    if (i < NN) {
        rowptr[i + 1] = base + sd[tid];        // inclusive end
        cursor[i] = base + sd[tid] - v;        // exclusive start
    }
    if (i == 0) rowptr[0] = 0;
}

__global__ void fill_kernel(const int* __restrict__ esrc, const int* __restrict__ edst,
                            int* __restrict__ cursor, int* __restrict__ srcsort) {
    int eid = blockIdx.x * blockDim.x + threadIdx.x;
    if (eid >= ET) return;
    int s, d;
    if (eid < EE) { s = esrc[eid]; d = edst[eid]; }
    else          { s = eid - EE; d = s; }
    int pos = atomicAdd(&cursor[d], 1);
    srcsort[pos] = s;
}

// ---------------- TF32 tensor-core GEMM: C = A[M,K] @ B[K,256] -----------------
#define BM 128
#define BN 128
#define SMS 136

__device__ __forceinline__ float f2tf(float x) {
    unsigned u;
    asm("cvt.rna.tf32.f32 %0, %1;" : "=r"(u) : "f"(x));
    return __uint_as_float(u);
}

__global__ __launch_bounds__(256) void tgemm_kernel(const float* __restrict__ A,
                                                    const float* __restrict__ B,
                                                    float* __restrict__ C,
                                                    int M, int K) {
    __shared__ float As[2][16][SMS];
    __shared__ float Bs[2][16][SMS];
    const int Nc = HC;

    int tid = threadIdx.x;
    int warp = tid >> 5, lane = tid & 31;
    int warpM = (warp & 3) * 32;
    int warpN = (warp >> 2) * 64;
    int cRow = blockIdx.y, cCol = blockIdx.x;
    int rowBase = cRow * BM;

    int aRow = tid >> 2;
    int aCol = (tid & 3) << 2;
    int bRow = tid >> 5;
    int bCol = (tid & 31) << 2;
    int gr0 = rowBase + aRow;
    int gr1 = gr0 + 64;
    const float* Bcol = B + cCol * BN + bCol;
    const float4 z4 = make_float4(0.f, 0.f, 0.f, 0.f);

    float4 a0, a1, b0, b1;

    a0 = (gr0 < M) ? *(const float4*)(A + (size_t)gr0 * K + aCol) : z4;
    a1 = (gr1 < M) ? *(const float4*)(A + (size_t)gr1 * K + aCol) : z4;
    b0 = *(const float4*)(Bcol + (size_t)bRow * Nc);
    b1 = *(const float4*)(Bcol + (size_t)(bRow + 8) * Nc);
    As[0][aCol + 0][aRow] = f2tf(a0.x);  As[0][aCol + 1][aRow] = f2tf(a0.y);
    As[0][aCol + 2][aRow] = f2tf(a0.z);  As[0][aCol + 3][aRow] = f2tf(a0.w);
    As[0][aCol + 0][aRow + 64] = f2tf(a1.x);  As[0][aCol + 1][aRow + 64] = f2tf(a1.y);
    As[0][aCol + 2][aRow + 64] = f2tf(a1.z);  As[0][aCol + 3][aRow + 64] = f2tf(a1.w);
    Bs[0][bRow][bCol + 0] = f2tf(b0.x);  Bs[0][bRow][bCol + 1] = f2tf(b0.y);
    Bs[0][bRow][bCol + 2] = f2tf(b0.z);  Bs[0][bRow][bCol + 3] = f2tf(b0.w);
    Bs[0][bRow + 8][bCol + 0] = f2tf(b1.x);  Bs[0][bRow + 8][bCol + 1] = f2tf(b1.y);
    Bs[0][bRow + 8][bCol + 2] = f2tf(b1.z);  Bs[0][bRow + 8][bCol + 3] = f2tf(b1.w);
    __syncthreads();

    float d[2][8][4];
#pragma unroll
    for (int i = 0; i < 2; i++)
#pragma unroll
        for (int j = 0; j < 8; j++)
#pragma unroll
            for (int q = 0; q < 4; q++) d[i][j][q] = 0.f;

    int T = K / 16;
    int lr = lane >> 2;
    int lc = lane & 3;

    for (int t = 0; t < T; t++) {
        int buf = t & 1;
        if (t + 1 < T) {
            int k0 = (t + 1) * 16;
            a0 = (gr0 < M) ? *(const float4*)(A + (size_t)gr0 * K + k0 + aCol) : z4;
            a1 = (gr1 < M) ? *(const float4*)(A + (size_t)gr1 * K + k0 + aCol) : z4;
            b0 = *(const float4*)(Bcol + (size_t)(k0 + bRow) * Nc);
            b1 = *(const float4*)(Bcol + (size_t)(k0 + bRow + 8) * Nc);
        }
#pragma unroll
        for (int ks = 0; ks < 16; ks += 8) {
            unsigned af[2][4], bf[8][2];
#pragma unroll
            for (int mt = 0; mt < 2; mt++) {
                int r = warpM + 16 * mt + lr;
                af[mt][0] = __float_as_uint(As[buf][ks + lc][r]);
                af[mt][1] = __float_as_uint(As[buf][ks + lc][r + 8]);
                af[mt][2] = __float_as_uint(As[buf][ks + 4 + lc][r]);
                af[mt][3] = __float_as_uint(As[buf][ks + 4 + lc][r + 8]);
            }
#pragma unroll
            for (int nt = 0; nt < 8; nt++) {
                int c = warpN + 8 * nt + lr;
                bf[nt][0] = __float_as_uint(Bs[buf][ks + lc][c]);
                bf[nt][1] = __float_as_uint(Bs[buf][ks + 4 + lc][c]);
            }
#pragma unroll
            for (int mt = 0; mt < 2; mt++)
#pragma unroll
                for (int nt = 0; nt < 8; nt++) {
                    asm volatile(
                        "mma.sync.aligned.m16n8k8.row.col.f32.tf32.tf32.f32 "
                        "{%0,%1,%2,%3}, {%4,%5,%6,%7}, {%8,%9}, {%0,%1,%2,%3};"
                        : "+f"(d[mt][nt][0]), "+f"(d[mt][nt][1]),
                          "+f"(d[mt][nt][2]), "+f"(d[mt][nt][3])
                        : "r"(af[mt][0]), "r"(af[mt][1]), "r"(af[mt][2]), "r"(af[mt][3]),
                          "r"(bf[nt][0]), "r"(bf[nt][1]));
                }
        }
        if (t + 1 < T) {
            int nb = buf ^ 1;
            As[nb][aCol + 0][aRow] = f2tf(a0.x);  As[nb][aCol + 1][aRow] = f2tf(a0.y);
            As[nb][aCol + 2][aRow] = f2tf(a0.z);  As[nb][aCol + 3][aRow] = f2tf(a0.w);
            As[nb][aCol + 0][aRow + 64] = f2tf(a1.x);  As[nb][aCol + 1][aRow + 64] = f2tf(a1.y);
            As[nb][aCol + 2][aRow + 64] = f2tf(a1.z);  As[nb][aCol + 3][aRow + 64] = f2tf(a1.w);
            Bs[nb][bRow][bCol + 0] = f2tf(b0.x);  Bs[nb][bRow][bCol + 1] = f2tf(b0.y);
            Bs[nb][bRow][bCol + 2] = f2tf(b0.z);  Bs[nb][bRow][bCol + 3] = f2tf(b0.w);
            Bs[nb][bRow + 8][bCol + 0] = f2tf(b1.x);  Bs[nb][bRow + 8][bCol + 1] = f2tf(b1.y);
            Bs[nb][bRow + 8][bCol + 2] = f2tf(b1.z);  Bs[nb][bRow + 8][bCol + 3] = f2tf(b1.w);
            __syncthreads();
        }
    }

#pragma unroll
    for (int mt = 0; mt < 2; mt++) {
        int r0 = rowBase + warpM + 16 * mt + lr;
        int r1 = r0 + 8;
#pragma unroll
        for (int nt = 0; nt < 8; nt++) {
            int c = cCol * BN + warpN + 8 * nt + 2 * lc;
            if (r0 < M)
                *(float2*)(C + (size_t)r0 * Nc + c) = make_float2(d[mt][nt][0], d[mt][nt][1]);
            if (r1 < M)
                *(float2*)(C + (size_t)r1 * Nc + c) = make_float2(d[mt][nt][2], d[mt][nt][3]);
        }
    }
}

// ---------------- per-node attention logits -----------------------------------
__global__ void asad_kernel(const float* __restrict__ h,
                            const float* __restrict__ att_src,
                            const float* __restrict__ att_dst,
                            float4* __restrict__ as_out,
                            float4* __restrict__ ad_out) {
    int warp = (blockIdx.x * blockDim.x + threadIdx.x) >> 5;
    int lid = threadIdx.x & 31;
    if (warp >= NN) return;
    const float* hr = h + (size_t)warp * HC;
    float ps[4] = {0.f, 0.f, 0.f, 0.f};
    float pd[4] = {0.f, 0.f, 0.f, 0.f};
#pragma unroll
    for (int k = 0; k < 8; k++) {
        int c = lid + 32 * k;
        float v = hr[c];
        ps[k >> 1] = fmaf(v, att_src[c], ps[k >> 1]);
        pd[k >> 1] = fmaf(v, att_dst[c], pd[k >> 1]);
    }
#pragma unroll
    for (int off = 16; off; off >>= 1) {
#pragma unroll
        for (int hh = 0; hh < 4; hh++) {
            ps[hh] += __shfl_xor_sync(0xFFFFFFFFu, ps[hh], off);
            pd[hh] += __shfl_xor_sync(0xFFFFFFFFu, pd[hh], off);
        }
    }
    if (lid == 0) {
        as_out[warp] = make_float4(ps[0], ps[1], ps[2], ps[3]);
        ad_out[warp] = make_float4(pd[0], pd[1], pd[2], pd[3]);
    }
}

// ---------------- fused edge-logit + softmax + aggregation + BN ---------------
__device__ __forceinline__ float4 leaky4(float4 a, float4 b) {
    float4 e;
    float v;
    v = a.x + b.x; e.x = (v > 0.f) ? v : SLOPE * v;
    v = a.y + b.y; e.y = (v > 0.f) ? v : SLOPE * v;
    v = a.z + b.z; e.z = (v > 0.f) ? v : SLOPE * v;
    v = a.w + b.w; e.w = (v > 0.f) ? v : SLOPE * v;
    return e;
}

__global__ __launch_bounds__(128) void agg_kernel(const int* __restrict__ srcsort,
                                                  const float* __restrict__ h,
                                                  const float4* __restrict__ as_in,
                                                  const float4* __restrict__ ad_in,
                                                  const int* __restrict__ rowptr,
                                                  float* __restrict__ y,
                                                  const float* __restrict__ bias,
                                                  const float* __restrict__ gam,
                                                  const float* __restrict__ bet,
                                                  const float* __restrict__ rmean,
                                                  const float* __restrict__ rvar) {
    int warp = (blockIdx.x * blockDim.x + threadIdx.x) >> 5;
    int lid = threadIdx.x & 31;
    if (warp >= NN) return;
    int beg = rowptr[warp], end = rowptr[warp + 1];
    float4 ad4 = ad_in[warp];                      // warp-uniform

    // pass 1: online softmax stats over incoming edges (lane-parallel)
    float m[4], s[4];
#pragma unroll
    for (int hh = 0; hh < 4; hh++) { m[hh] = -1e30f; s[hh] = 0.f; }

    for (int j = beg + lid; j < end; j += 32) {
        int src = srcsort[j];                      // contiguous
        float4 e4 = leaky4(as_in[src], ad4);       // 16B gather (L2-resident)
        float ev[4] = {e4.x, e4.y, e4.z, e4.w};
#pragma unroll
        for (int hh = 0; hh < 4; hh++) {
            float mn = fmaxf(m[hh], ev[hh]);
            s[hh] = s[hh] * __expf(m[hh] - mn) + __expf(ev[hh] - mn);
            m[hh] = mn;
        }
    }
#pragma unroll
    for (int off = 16; off; off >>= 1) {
#pragma unroll
        for (int hh = 0; hh < 4; hh++) {
            float mo = __shfl_xor_sync(0xFFFFFFFFu, m[hh], off);
            float so = __shfl_xor_sync(0xFFFFFFFFu, s[hh], off);
            float mn = fmaxf(m[hh], mo);
            s[hh] = s[hh] * __expf(m[hh] - mn) + so * __expf(mo - mn);
            m[hh] = mn;
        }
    }
    float inv[4];
#pragma unroll
    for (int hh = 0; hh < 4; hh++) inv[hh] = 1.f / s[hh];

    // pass 2: weighted message aggregation (warp-cooperative per edge)
    float acc[8] = {0.f, 0.f, 0.f, 0.f, 0.f, 0.f, 0.f, 0.f};
    for (int j = beg; j < end; j++) {
        int src = srcsort[j];                      // broadcast
        float4 e4 = leaky4(as_in[src], ad4);       // broadcast 16B load
        float al[4] = {__expf(e4.x - m[0]) * inv[0], __expf(e4.y - m[1]) * inv[1],
                       __expf(e4.z - m[2]) * inv[2], __expf(e4.w - m[3]) * inv[3]};
        const float* hs = h + (size_t)src * HC;
#pragma unroll
        for (int k = 0; k < 8; k++)
            acc[k] = fmaf(hs[lid + 32 * k], al[k >> 1], acc[k]);
    }

    size_t ob = (size_t)warp * HC;
#pragma unroll
    for (int k = 0; k < 8; k++) {
        int c = lid + 32 * k;
        float v = acc[k] + bias[c];
        v = fmaxf(v, 0.f);
        v = (v - rmean[c]) * rsqrtf(rvar[c] + BNEPS) * gam[c] + bet[c];
        y[ob + c] = v;
    }
}

// ---------------- pooling ------------------------------------------------------
__device__ __forceinline__ int lowerb(const int* b, int n, int key) {
    int lo = 0, hi = n;
    while (lo < hi) {
        int mid = (lo + hi) >> 1;
        if (b[mid] < key) lo = mid + 1; else hi = mid;
    }
    return lo;
}

__global__ void pool_kernel(const int* __restrict__ batch,
                            const float* __restrict__ y,
                            float* __restrict__ pooled) {
    int g = blockIdx.x;
    int c = threadIdx.x;
    __shared__ int s_lo, s_hi;
    if (c == 0) {
        s_lo = lowerb(batch, NN, g);
        s_hi = lowerb(batch, NN, g + 1);
    }
    __syncthreads();
    float sum = 0.f;
    for (int n = s_lo; n < s_hi; n++) sum += y[(size_t)n * HC + c];
    int cnt = s_hi - s_lo;
    float denom = (cnt > 0) ? (float)cnt : 1.f;
    pooled[g * HC + c] = sum / denom;
}

// ---------------- MLP head -----------------------------------------------------
__global__ void head_kernel(const float* __restrict__ pooled,
                            const float* __restrict__ lw1, const float* __restrict__ lb1,
                            const float* __restrict__ lw2, const float* __restrict__ lb2,
                            float* __restrict__ out) {
    int g = blockIdx.x;
    int j = threadIdx.x;
    __shared__ float sp[256];
    __shared__ float r0[128], r1[128];
    sp[j] = pooled[g * HC + j];
    sp[j + 128] = pooled[g * HC + 128 + j];
    __syncthreads();
    float z = lb1[j];
#pragma unroll 4
    for (int k = 0; k < 256; k++) z = fmaf(sp[k], lw1[k * 128 + j], z);
    z = fmaxf(z, 0.f);
    r0[j] = z * lw2[j * 2 + 0];
    r1[j] = z * lw2[j * 2 + 1];
    __syncthreads();
    for (int off = 64; off; off >>= 1) {
        if (j < off) { r0[j] += r0[j + off]; r1[j] += r1[j + off]; }
        __syncthreads();
    }
    if (j == 0) {
        out[g * 2 + 0] = r0[0] + lb2[0];
        out[g * 2 + 1] = r1[0] + lb2[1];
    }
}

// ---------------- launcher ------------------------------------------------------
extern "C" void kernel_launch(void* const* d_in, const int* in_sizes, int n_in,
                              void* d_out, int out_size) {
    const float* x        = (const float*)d_in[0];
    const void*  ei       = d_in[1];
    const void*  batchraw = d_in[2];
    const float* W1       = (const float*)d_in[3];
    const float* att_src1 = (const float*)d_in[4];
    const float* att_dst1 = (const float*)d_in[5];
    const float* b1       = (const float*)d_in[6];
    const float* g1       = (const float*)d_in[7];
    const float* be1      = (const float*)d_in[8];
    const float* rm1      = (const float*)d_in[9];
    const float* rv1      = (const float*)d_in[10];
    const float* W2       = (const float*)d_in[11];
    const float* att_src2 = (const float*)d_in[12];
    const float* att_dst2 = (const float*)d_in[13];
    const float* b2       = (const float*)d_in[14];
    const float* g2       = (const float*)d_in[15];
    const float* be2      = (const float*)d_in[16];
    const float* rm2      = (const float*)d_in[17];
    const float* rv2      = (const float*)d_in[18];
    const float* lw1      = (const float*)d_in[19];
    const float* lb1      = (const float*)d_in[20];
    const float* lw2      = (const float*)d_in[21];
    const float* lb2      = (const float*)d_in[22];

    float*  p_h = nullptr;  float*  p_y = nullptr;  float4* p_as = nullptr;
    float4* p_ad = nullptr; int* p_deg = nullptr;
    int* p_rowptr = nullptr; int* p_cursor = nullptr; int* p_srcsort = nullptr;
    float* p_pooled = nullptr; int* p_src = nullptr; int* p_dst = nullptr;
    int* p_batch = nullptr; int* p_is64 = nullptr;
    int* p_bsum = nullptr; int* p_boff = nullptr;
    cudaGetSymbolAddress((void**)&p_h, g_h);
    cudaGetSymbolAddress((void**)&p_y, g_y);
    cudaGetSymbolAddress((void**)&p_as, g_as);
    cudaGetSymbolAddress((void**)&p_ad, g_ad);
    cudaGetSymbolAddress((void**)&p_deg, g_deg);
    cudaGetSymbolAddress((void**)&p_rowptr, g_rowptr);
    cudaGetSymbolAddress((void**)&p_cursor, g_cursor);
    cudaGetSymbolAddress((void**)&p_srcsort, g_srcsort);
    cudaGetSymbolAddress((void**)&p_pooled, g_pooled);
    cudaGetSymbolAddress((void**)&p_src, g_src);
    cudaGetSymbolAddress((void**)&p_dst, g_dst);
    cudaGetSymbolAddress((void**)&p_batch, g_batch);
    cudaGetSymbolAddress((void**)&p_is64, g_is64);
    cudaGetSymbolAddress((void**)&p_bsum, g_bsum);
    cudaGetSymbolAddress((void**)&p_boff, g_boff);

    dim3 ggrid(HC / BN, (NN + BM - 1) / BM);
    int aggBlocks = (NN * 32 + 127) / 128;
    int warpBlocks = (NN * 32 + 255) / 256;

    // (1) detect (2) prep (3) count (4) tgemm1 <- profiled slot (sentinel)
    detect_kernel<<<1, 1024>>>((const unsigned*)ei, p_is64);
    prep_kernel<<<(EE + 255) / 256, 256>>>(ei, batchraw, p_is64, p_src, p_dst,
                                           p_batch, p_deg);
    count_kernel<<<(ET + 255) / 256, 256>>>(p_dst, p_deg);
    tgemm_kernel<<<ggrid, 256>>>(x, W1, p_h, NN, FIN);

    // hierarchical scan + fill
    blocksum_kernel<<<NB, SCAN_B>>>(p_deg, p_bsum);
    scanb_kernel<<<1, 256>>>(p_bsum, p_boff);
    scatter_kernel<<<NB, SCAN_B>>>(p_deg, p_boff, p_rowptr, p_cursor);
    fill_kernel<<<(ET + 255) / 256, 256>>>(p_src, p_dst, p_cursor, p_srcsort);

    // ---- layer 1 ----
    asad_kernel<<<warpBlocks, 256>>>(p_h, att_src1, att_dst1, p_as, p_ad);
    agg_kernel<<<aggBlocks, 128>>>(p_srcsort, p_h, p_as, p_ad, p_rowptr, p_y,
                                   b1, g1, be1, rm1, rv1);

    // ---- layer 2 ----
    tgemm_kernel<<<ggrid, 256>>>(p_y, W2, p_h, NN, HC);
    asad_kernel<<<warpBlocks, 256>>>(p_h, att_src2, att_dst2, p_as, p_ad);
    agg_kernel<<<aggBlocks, 128>>>(p_srcsort, p_h, p_as, p_ad, p_rowptr, p_y,
                                   b2, g2, be2, rm2, rv2);

    // ---- pool + head ----
    pool_kernel<<<NG, 256>>>(p_batch, p_y, p_pooled);
    head_kernel<<<NG, 128>>>(p_pooled, lw1, lb1, lw2, lb2, (float*)d_out);
}

// round 9
// speedup vs baseline: 2.2312x; 1.2721x over previous
#include <cuda_runtime.h>
#include <cuda_fp16.h>
#include <math.h>

#define NN 50000
#define EE 800000
#define ET 850000      // EE + NN self loops
#define FIN 128
#define HC 256         // HEADS*HID
#define NG 500
#define SLOPE 0.2f
#define BNEPS 1e-5f

// ---------------- scratch (device globals; no runtime allocation) -------------
__device__ __align__(256) __half g_hh[(size_t)NN * HC];  // GEMM output (fp16)
__device__ __align__(256) float  g_y[(size_t)NN * HC];   // layer output (fp32)
__device__ float4 g_as[NN];
__device__ float4 g_ad[NN];
__device__ int    g_srcsort[ET];
__device__ int    g_deg[NN];
__device__ int    g_rowptr[NN + 1];
__device__ int    g_cursor[NN];
__device__ __align__(256) float  g_pooled[NG * HC];
__device__ int    g_src[EE];
__device__ int    g_dst[EE];
__device__ int    g_batch[NN];
__device__ int    g_is64;
#define SCAN_B 256
#define NB ((NN + SCAN_B - 1) / SCAN_B)    // 196
__device__ int    g_bsum[NB];
__device__ int    g_boff[NB];

// ---------------- dtype detect ------------------------------------------------
__global__ void detect_kernel(const unsigned* __restrict__ eiw, int* __restrict__ is64) {
    __shared__ int s_any;
    if (threadIdx.x == 0) s_any = 0;
    __syncthreads();
    unsigned v = eiw[threadIdx.x * 2 + 1];
    if (v != 0u) atomicOr(&s_any, 1);
    __syncthreads();
    if (threadIdx.x == 0) *is64 = s_any ? 0 : 1;
}

// ---------------- init deg = 1 (self loop) ------------------------------------
__global__ void initdeg_kernel(int* __restrict__ deg) {
    int i = blockIdx.x * blockDim.x + threadIdx.x;
    if (i < NN) deg[i] = 1;
}

// ---------------- prep: index conversion + batch + degree count ----------------
__global__ void prep_kernel(const void* __restrict__ ei, const void* __restrict__ b,
                            const int* __restrict__ is64,
                            int* __restrict__ src, int* __restrict__ dst,
                            int* __restrict__ batch, int* __restrict__ deg) {
    int i = blockIdx.x * blockDim.x + threadIdx.x;
    int w = *is64;
    if (i < EE) {
        int s, d;
        if (w) {
            const long long* p = (const long long*)ei;
            s = (int)p[i];
            d = (int)p[EE + i];
        } else {
            const int* p = (const int*)ei;
            s = p[i];
            d = p[EE + i];
        }
        src[i] = s;
        dst[i] = d;
        atomicAdd(&deg[d], 1);
    }
    if (i < NN) {
        batch[i] = w ? (int)((const long long*)b)[i] : ((const int*)b)[i];
    }
}

// ---------------- hierarchical scan -------------------------------------------
__global__ void blocksum_kernel(const int* __restrict__ deg, int* __restrict__ bsum) {
    __shared__ int sd[SCAN_B];
    int tid = threadIdx.x;
    int i = blockIdx.x * SCAN_B + tid;
    sd[tid] = (i < NN) ? deg[i] : 0;
    __syncthreads();
    for (int off = SCAN_B / 2; off; off >>= 1) {
        if (tid < off) sd[tid] += sd[tid + off];
        __syncthreads();
    }
    if (tid == 0) bsum[blockIdx.x] = sd[0];
}

__global__ void scanb_kernel(const int* __restrict__ bsum, int* __restrict__ boff) {
    __shared__ int sd[256];
    int tid = threadIdx.x;
    int v = (tid < NB) ? bsum[tid] : 0;
    sd[tid] = v;
    __syncthreads();
    for (int off = 1; off < 256; off <<= 1) {
        int t = (tid >= off) ? sd[tid - off] : 0;
        __syncthreads();
        sd[tid] += t;
        __syncthreads();
    }
    if (tid < NB) boff[tid] = sd[tid] - v;
}

__global__ void scatter_kernel(const int* __restrict__ deg, const int* __restrict__ boff,
                               int* __restrict__ rowptr, int* __restrict__ cursor) {
    __shared__ int sd[SCAN_B];
    int tid = threadIdx.x;
    int i = blockIdx.x * SCAN_B + tid;
    int v = (i < NN) ? deg[i] : 0;
    sd[tid] = v;
    __syncthreads();
    for (int off = 1; off < SCAN_B; off <<= 1) {
        int t = (tid >= off) ? sd[tid - off] : 0;
        __syncthreads();
        sd[tid] += t;
        __syncthreads();
    }
    int base = boff[blockIdx.x];
    if (i < NN) {
        rowptr[i + 1] = base + sd[tid];
        cursor[i] = base + sd[tid] - v;
    }
    if (i == 0) rowptr[0] = 0;
}

__global__ void fill_kernel(const int* __restrict__ esrc, const int* __restrict__ edst,
                            int* __restrict__ cursor, int* __restrict__ srcsort) {
    int eid = blockIdx.x * blockDim.x + threadIdx.x;
    if (eid >= ET) return;
    int s, d;
    if (eid < EE) { s = esrc[eid]; d = edst[eid]; }
    else          { s = eid - EE; d = s; }
    int pos = atomicAdd(&cursor[d], 1);
    srcsort[pos] = s;
}

// ---------------- TF32 tensor-core GEMM: C(half) = A[M,K] @ B[K,256] -----------
#define BM 128
#define BN 128
#define SMS 136

__device__ __forceinline__ float f2tf(float x) {
    unsigned u;
    asm("cvt.rna.tf32.f32 %0, %1;" : "=r"(u) : "f"(x));
    return __uint_as_float(u);
}

__global__ __launch_bounds__(256) void tgemm_kernel(const float* __restrict__ A,
                                                    const float* __restrict__ B,
                                                    __half* __restrict__ C,
                                                    int M, int K) {
    __shared__ float As[2][16][SMS];
    __shared__ float Bs[2][16][SMS];
    const int Nc = HC;

    int tid = threadIdx.x;
    int warp = tid >> 5, lane = tid & 31;
    int warpM = (warp & 3) * 32;
    int warpN = (warp >> 2) * 64;
    int cRow = blockIdx.y, cCol = blockIdx.x;
    int rowBase = cRow * BM;

    int aRow = tid >> 2;
    int aCol = (tid & 3) << 2;
    int bRow = tid >> 5;
    int bCol = (tid & 31) << 2;
    int gr0 = rowBase + aRow;
    int gr1 = gr0 + 64;
    const float* Bcol = B + cCol * BN + bCol;
    const float4 z4 = make_float4(0.f, 0.f, 0.f, 0.f);

    float4 a0, a1, b0, b1;

    a0 = (gr0 < M) ? *(const float4*)(A + (size_t)gr0 * K + aCol) : z4;
    a1 = (gr1 < M) ? *(const float4*)(A + (size_t)gr1 * K + aCol) : z4;
    b0 = *(const float4*)(Bcol + (size_t)bRow * Nc);
    b1 = *(const float4*)(Bcol + (size_t)(bRow + 8) * Nc);
    As[0][aCol + 0][aRow] = f2tf(a0.x);  As[0][aCol + 1][aRow] = f2tf(a0.y);
    As[0][aCol + 2][aRow] = f2tf(a0.z);  As[0][aCol + 3][aRow] = f2tf(a0.w);
    As[0][aCol + 0][aRow + 64] = f2tf(a1.x);  As[0][aCol + 1][aRow + 64] = f2tf(a1.y);
    As[0][aCol + 2][aRow + 64] = f2tf(a1.z);  As[0][aCol + 3][aRow + 64] = f2tf(a1.w);
    Bs[0][bRow][bCol + 0] = f2tf(b0.x);  Bs[0][bRow][bCol + 1] = f2tf(b0.y);
    Bs[0][bRow][bCol + 2] = f2tf(b0.z);  Bs[0][bRow][bCol + 3] = f2tf(b0.w);
    Bs[0][bRow + 8][bCol + 0] = f2tf(b1.x);  Bs[0][bRow + 8][bCol + 1] = f2tf(b1.y);
    Bs[0][bRow + 8][bCol + 2] = f2tf(b1.z);  Bs[0][bRow + 8][bCol + 3] = f2tf(b1.w);
    __syncthreads();

    float d[2][8][4];
#pragma unroll
    for (int i = 0; i < 2; i++)
#pragma unroll
        for (int j = 0; j < 8; j++)
#pragma unroll
            for (int q = 0; q < 4; q++) d[i][j][q] = 0.f;

    int T = K / 16;
    int lr = lane >> 2;
    int lc = lane & 3;

    for (int t = 0; t < T; t++) {
        int buf = t & 1;
        if (t + 1 < T) {
            int k0 = (t + 1) * 16;
            a0 = (gr0 < M) ? *(const float4*)(A + (size_t)gr0 * K + k0 + aCol) : z4;
            a1 = (gr1 < M) ? *(const float4*)(A + (size_t)gr1 * K + k0 + aCol) : z4;
            b0 = *(const float4*)(Bcol + (size_t)(k0 + bRow) * Nc);
            b1 = *(const float4*)(Bcol + (size_t)(k0 + bRow + 8) * Nc);
        }
#pragma unroll
        for (int ks = 0; ks < 16; ks += 8) {
            unsigned af[2][4], bf[8][2];
#pragma unroll
            for (int mt = 0; mt < 2; mt++) {
                int r = warpM + 16 * mt + lr;
                af[mt][0] = __float_as_uint(As[buf][ks + lc][r]);
                af[mt][1] = __float_as_uint(As[buf][ks + lc][r + 8]);
                af[mt][2] = __float_as_uint(As[buf][ks + 4 + lc][r]);
                af[mt][3] = __float_as_uint(As[buf][ks + 4 + lc][r + 8]);
            }
#pragma unroll
            for (int nt = 0; nt < 8; nt++) {
                int c = warpN + 8 * nt + lr;
                bf[nt][0] = __float_as_uint(Bs[buf][ks + lc][c]);
                bf[nt][1] = __float_as_uint(Bs[buf][ks + 4 + lc][c]);
            }
#pragma unroll
            for (int mt = 0; mt < 2; mt++)
#pragma unroll
                for (int nt = 0; nt < 8; nt++) {
                    asm volatile(
                        "mma.sync.aligned.m16n8k8.row.col.f32.tf32.tf32.f32 "
                        "{%0,%1,%2,%3}, {%4,%5,%6,%7}, {%8,%9}, {%0,%1,%2,%3};"
                        : "+f"(d[mt][nt][0]), "+f"(d[mt][nt][1]),
                          "+f"(d[mt][nt][2]), "+f"(d[mt][nt][3])
                        : "r"(af[mt][0]), "r"(af[mt][1]), "r"(af[mt][2]), "r"(af[mt][3]),
                          "r"(bf[nt][0]), "r"(bf[nt][1]));
                }
        }
        if (t + 1 < T) {
            int nb = buf ^ 1;
            As[nb][aCol + 0][aRow] = f2tf(a0.x);  As[nb][aCol + 1][aRow] = f2tf(a0.y);
            As[nb][aCol + 2][aRow] = f2tf(a0.z);  As[nb][aCol + 3][aRow] = f2tf(a0.w);
            As[nb][aCol + 0][aRow + 64] = f2tf(a1.x);  As[nb][aCol + 1][aRow + 64] = f2tf(a1.y);
            As[nb][aCol + 2][aRow + 64] = f2tf(a1.z);  As[nb][aCol + 3][aRow + 64] = f2tf(a1.w);
            Bs[nb][bRow][bCol + 0] = f2tf(b0.x);  Bs[nb][bRow][bCol + 1] = f2tf(b0.y);
            Bs[nb][bRow][bCol + 2] = f2tf(b0.z);  Bs[nb][bRow][bCol + 3] = f2tf(b0.w);
            Bs[nb][bRow + 8][bCol + 0] = f2tf(b1.x);  Bs[nb][bRow + 8][bCol + 1] = f2tf(b1.y);
            Bs[nb][bRow + 8][bCol + 2] = f2tf(b1.z);  Bs[nb][bRow + 8][bCol + 3] = f2tf(b1.w);
            __syncthreads();
        }
    }

    // epilogue: store as fp16 pairs
#pragma unroll
    for (int mt = 0; mt < 2; mt++) {
        int r0 = rowBase + warpM + 16 * mt + lr;
        int r1 = r0 + 8;
#pragma unroll
        for (int nt = 0; nt < 8; nt++) {
            int c = cCol * BN + warpN + 8 * nt + 2 * lc;
            if (r0 < M)
                *(__half2*)(C + (size_t)r0 * Nc + c) = __floats2half2_rn(d[mt][nt][0], d[mt][nt][1]);
            if (r1 < M)
                *(__half2*)(C + (size_t)r1 * Nc + c) = __floats2half2_rn(d[mt][nt][2], d[mt][nt][3]);
        }
    }
}

// ---------------- per-node attention logits (fp16 h) ---------------------------
__global__ void asad_kernel(const __half* __restrict__ hh,
                            const float* __restrict__ att_src,
                            const float* __restrict__ att_dst,
                            float4* __restrict__ as_out,
                            float4* __restrict__ ad_out) {
    int warp = (blockIdx.x * blockDim.x + threadIdx.x) >> 5;
    int lid = threadIdx.x & 31;
    if (warp >= NN) return;
    const __half2* hr = (const __half2*)(hh + (size_t)warp * HC);
    float ps[4], pd[4];
#pragma unroll
    for (int k = 0; k < 4; k++) { ps[k] = 0.f; pd[k] = 0.f; }
#pragma unroll
    for (int k = 0; k < 4; k++) {
        float2 v = __half22float2(hr[lid + 32 * k]);
        int c = 2 * lid + 64 * k;
        float2 s2 = *(const float2*)(att_src + c);
        float2 d2 = *(const float2*)(att_dst + c);
        ps[k] = fmaf(v.x, s2.x, fmaf(v.y, s2.y, ps[k]));
        pd[k] = fmaf(v.x, d2.x, fmaf(v.y, d2.y, pd[k]));
    }
#pragma unroll
    for (int off = 16; off; off >>= 1) {
#pragma unroll
        for (int k = 0; k < 4; k++) {
            ps[k] += __shfl_xor_sync(0xFFFFFFFFu, ps[k], off);
            pd[k] += __shfl_xor_sync(0xFFFFFFFFu, pd[k], off);
        }
    }
    if (lid == 0) {
        as_out[warp] = make_float4(ps[0], ps[1], ps[2], ps[3]);
        ad_out[warp] = make_float4(pd[0], pd[1], pd[2], pd[3]);
    }
}

// ---------------- fused single-pass softmax-aggregation + bias + relu + BN -----
__device__ __forceinline__ float4 leaky4(float4 a, float4 b) {
    float4 e;
    float v;
    v = a.x + b.x; e.x = (v > 0.f) ? v : SLOPE * v;
    v = a.y + b.y; e.y = (v > 0.f) ? v : SLOPE * v;
    v = a.z + b.z; e.z = (v > 0.f) ? v : SLOPE * v;
    v = a.w + b.w; e.w = (v > 0.f) ? v : SLOPE * v;
    return e;
}

__global__ __launch_bounds__(128) void agg_kernel(const int* __restrict__ srcsort,
                                                  const __half* __restrict__ hh,
                                                  const float4* __restrict__ as_in,
                                                  const float4* __restrict__ ad_in,
                                                  const int* __restrict__ rowptr,
                                                  float* __restrict__ y,
                                                  const float* __restrict__ bias,
                                                  const float* __restrict__ gam,
                                                  const float* __restrict__ bet,
                                                  const float* __restrict__ rmean,
                                                  const float* __restrict__ rvar) {
    int warp = (blockIdx.x * blockDim.x + threadIdx.x) >> 5;
    int lid = threadIdx.x & 31;
    if (warp >= NN) return;
    int beg = rowptr[warp], end = rowptr[warp + 1];
    float4 ad4 = ad_in[warp];

    float accx[4] = {0.f, 0.f, 0.f, 0.f};
    float accy[4] = {0.f, 0.f, 0.f, 0.f};
    float sp[4] = {0.f, 0.f, 0.f, 0.f};   // per-lane partial sum of exp

    for (int base = beg; base < end; base += 32) {
        int j = base + lid;
        bool valid = j < end;
        int src = valid ? srcsort[j] : 0;
        // lane-parallel exp over distinct edges (unnormalized softmax; logits small)
        float4 e4 = leaky4(as_in[src], ad4);
        float4 al;
        al.x = valid ? __expf(e4.x) : 0.f;
        al.y = valid ? __expf(e4.y) : 0.f;
        al.z = valid ? __expf(e4.z) : 0.f;
        al.w = valid ? __expf(e4.w) : 0.f;
        sp[0] += al.x; sp[1] += al.y; sp[2] += al.z; sp[3] += al.w;

        int nn = min(32, end - base);
        for (int i = 0; i < nn; i++) {
            int sj   = __shfl_sync(0xFFFFFFFFu, src, i);
            float a0 = __shfl_sync(0xFFFFFFFFu, al.x, i);
            float a1 = __shfl_sync(0xFFFFFFFFu, al.y, i);
            float a2 = __shfl_sync(0xFFFFFFFFu, al.z, i);
            float a3 = __shfl_sync(0xFFFFFFFFu, al.w, i);
            const __half2* hs = (const __half2*)(hh + (size_t)sj * HC);
            float2 v0 = __half22float2(hs[lid]);
            float2 v1 = __half22float2(hs[lid + 32]);
            float2 v2 = __half22float2(hs[lid + 64]);
            float2 v3 = __half22float2(hs[lid + 96]);
            accx[0] = fmaf(v0.x, a0, accx[0]);  accy[0] = fmaf(v0.y, a0, accy[0]);
            accx[1] = fmaf(v1.x, a1, accx[1]);  accy[1] = fmaf(v1.y, a1, accy[1]);
            accx[2] = fmaf(v2.x, a2, accx[2]);  accy[2] = fmaf(v2.y, a2, accy[2]);
            accx[3] = fmaf(v3.x, a3, accx[3]);  accy[3] = fmaf(v3.y, a3, accy[3]);
        }
    }

    // reduce exp sums across lanes
#pragma unroll
    for (int off = 16; off; off >>= 1) {
#pragma unroll
        for (int k = 0; k < 4; k++)
            sp[k] += __shfl_xor_sync(0xFFFFFFFFu, sp[k], off);
    }
    float inv[4];
#pragma unroll
    for (int k = 0; k < 4; k++) inv[k] = 1.f / sp[k];

    size_t ob = (size_t)warp * HC;
#pragma unroll
    for (int k = 0; k < 4; k++) {
        int c = 2 * lid + 64 * k;
        float2 bi = *(const float2*)(bias + c);
        float2 ga = *(const float2*)(gam + c);
        float2 be = *(const float2*)(bet + c);
        float2 rm = *(const float2*)(rmean + c);
        float2 rv = *(const float2*)(rvar + c);
        float vx = fmaxf(accx[k] * inv[k] + bi.x, 0.f);
        float vy = fmaxf(accy[k] * inv[k] + bi.y, 0.f);
        vx = (vx - rm.x) * rsqrtf(rv.x + BNEPS) * ga.x + be.x;
        vy = (vy - rm.y) * rsqrtf(rv.y + BNEPS) * ga.y + be.y;
        *(float2*)(y + ob + c) = make_float2(vx, vy);
    }
}

// ---------------- pooling ------------------------------------------------------
__device__ __forceinline__ int lowerb(const int* b, int n, int key) {
    int lo = 0, hi = n;
    while (lo < hi) {
        int mid = (lo + hi) >> 1;
        if (b[mid] < key) lo = mid + 1; else hi = mid;
    }
    return lo;
}

__global__ void pool_kernel(const int* __restrict__ batch,
                            const float* __restrict__ y,
                            float* __restrict__ pooled) {
    int g = blockIdx.x;
    int c = threadIdx.x;
    __shared__ int s_lo, s_hi;
    if (c == 0) {
        s_lo = lowerb(batch, NN, g);
        s_hi = lowerb(batch, NN, g + 1);
    }
    __syncthreads();
    float sum = 0.f;
    for (int n = s_lo; n < s_hi; n++) sum += y[(size_t)n * HC + c];
    int cnt = s_hi - s_lo;
    float denom = (cnt > 0) ? (float)cnt : 1.f;
    pooled[g * HC + c] = sum / denom;
}

// ---------------- MLP head -----------------------------------------------------
__global__ void head_kernel(const float* __restrict__ pooled,
                            const float* __restrict__ lw1, const float* __restrict__ lb1,
                            const float* __restrict__ lw2, const float* __restrict__ lb2,
                            float* __restrict__ out) {
    int g = blockIdx.x;
    int j = threadIdx.x;
    __shared__ float sp[256];
    __shared__ float r0[128], r1[128];
    sp[j] = pooled[g * HC + j];
    sp[j + 128] = pooled[g * HC + 128 + j];
    __syncthreads();
    float z = lb1[j];
#pragma unroll 4
    for (int k = 0; k < 256; k++) z = fmaf(sp[k], lw1[k * 128 + j], z);
    z = fmaxf(z, 0.f);
    r0[j] = z * lw2[j * 2 + 0];
    r1[j] = z * lw2[j * 2 + 1];
    __syncthreads();
    for (int off = 64; off; off >>= 1) {
        if (j < off) { r0[j] += r0[j + off]; r1[j] += r1[j + off]; }
        __syncthreads();
    }
    if (j == 0) {
        out[g * 2 + 0] = r0[0] + lb2[0];
        out[g * 2 + 1] = r1[0] + lb2[1];
    }
}

// ---------------- launcher ------------------------------------------------------
extern "C" void kernel_launch(void* const* d_in, const int* in_sizes, int n_in,
                              void* d_out, int out_size) {
    const float* x        = (const float*)d_in[0];
    const void*  ei       = d_in[1];
    const void*  batchraw = d_in[2];
    const float* W1       = (const float*)d_in[3];
    const float* att_src1 = (const float*)d_in[4];
    const float* att_dst1 = (const float*)d_in[5];
    const float* b1       = (const float*)d_in[6];
    const float* g1       = (const float*)d_in[7];
    const float* be1      = (const float*)d_in[8];
    const float* rm1      = (const float*)d_in[9];
    const float* rv1      = (const float*)d_in[10];
    const float* W2       = (const float*)d_in[11];
    const float* att_src2 = (const float*)d_in[12];
    const float* att_dst2 = (const float*)d_in[13];
    const float* b2       = (const float*)d_in[14];
    const float* g2       = (const float*)d_in[15];
    const float* be2      = (const float*)d_in[16];
    const float* rm2      = (const float*)d_in[17];
    const float* rv2      = (const float*)d_in[18];
    const float* lw1      = (const float*)d_in[19];
    const float* lb1      = (const float*)d_in[20];
    const float* lw2      = (const float*)d_in[21];
    const float* lb2      = (const float*)d_in[22];

    __half* p_hh = nullptr; float* p_y = nullptr; float4* p_as = nullptr;
    float4* p_ad = nullptr; int* p_deg = nullptr;
    int* p_rowptr = nullptr; int* p_cursor = nullptr; int* p_srcsort = nullptr;
    float* p_pooled = nullptr; int* p_src = nullptr; int* p_dst = nullptr;
    int* p_batch = nullptr; int* p_is64 = nullptr;
    int* p_bsum = nullptr; int* p_boff = nullptr;
    cudaGetSymbolAddress((void**)&p_hh, g_hh);
    cudaGetSymbolAddress((void**)&p_y, g_y);
    cudaGetSymbolAddress((void**)&p_as, g_as);
    cudaGetSymbolAddress((void**)&p_ad, g_ad);
    cudaGetSymbolAddress((void**)&p_deg, g_deg);
    cudaGetSymbolAddress((void**)&p_rowptr, g_rowptr);
    cudaGetSymbolAddress((void**)&p_cursor, g_cursor);
    cudaGetSymbolAddress((void**)&p_srcsort, g_srcsort);
    cudaGetSymbolAddress((void**)&p_pooled, g_pooled);
    cudaGetSymbolAddress((void**)&p_src, g_src);
    cudaGetSymbolAddress((void**)&p_dst, g_dst);
    cudaGetSymbolAddress((void**)&p_batch, g_batch);
    cudaGetSymbolAddress((void**)&p_is64, g_is64);
    cudaGetSymbolAddress((void**)&p_bsum, g_bsum);
    cudaGetSymbolAddress((void**)&p_boff, g_boff);

    dim3 ggrid(HC / BN, (NN + BM - 1) / BM);
    int aggBlocks = (NN * 32 + 127) / 128;
    int warpBlocks = (NN * 32 + 255) / 256;

    // (1) detect (2) initdeg (3) prep(+count) (4) tgemm1 <- profiled sentinel
    detect_kernel<<<1, 1024>>>((const unsigned*)ei, p_is64);
    initdeg_kernel<<<(NN + 255) / 256, 256>>>(p_deg);
    prep_kernel<<<(EE + 255) / 256, 256>>>(ei, batchraw, p_is64, p_src, p_dst,
                                           p_batch, p_deg);
    tgemm_kernel<<<ggrid, 256>>>(x, W1, p_hh, NN, FIN);

    // hierarchical scan + fill
    blocksum_kernel<<<NB, SCAN_B>>>(p_deg, p_bsum);
    scanb_kernel<<<1, 256>>>(p_bsum, p_boff);
    scatter_kernel<<<NB, SCAN_B>>>(p_deg, p_boff, p_rowptr, p_cursor);
    fill_kernel<<<(ET + 255) / 256, 256>>>(p_src, p_dst, p_cursor, p_srcsort);

    // ---- layer 1 ----
    asad_kernel<<<warpBlocks, 256>>>(p_hh, att_src1, att_dst1, p_as, p_ad);
    agg_kernel<<<aggBlocks, 128>>>(p_srcsort, p_hh, p_as, p_ad, p_rowptr, p_y,
                                   b1, g1, be1, rm1, rv1);

    // ---- layer 2 ----
    tgemm_kernel<<<ggrid, 256>>>(p_y, W2, p_hh, NN, HC);
    asad_kernel<<<warpBlocks, 256>>>(p_hh, att_src2, att_dst2, p_as, p_ad);
    agg_kernel<<<aggBlocks, 128>>>(p_srcsort, p_hh, p_as, p_ad, p_rowptr, p_y,
                                   b2, g2, be2, rm2, rv2);

    // ---- pool + head ----
    pool_kernel<<<NG, 256>>>(p_batch, p_y, p_pooled);
    head_kernel<<<NG, 128>>>(p_pooled, lw1, lb1, lw2, lb2, (float*)d_out);
}

// round 10
// speedup vs baseline: 2.3718x; 1.0630x over previous
#include <cuda_runtime.h>
#include <cuda_fp16.h>
#include <math.h>

#define NN 50000
#define EE 800000
#define ET 850000      // EE + NN self loops
#define FIN 128
#define HC 256         // HEADS*HID
#define NG 500
#define SLOPE 0.2f
#define BNEPS 1e-5f

// ---------------- scratch (device globals; no runtime allocation) -------------
__device__ __align__(256) __half g_hh[(size_t)NN * HC];   // GEMM output (fp16)
__device__ __align__(256) __half g_yh[(size_t)NN * HC];   // layer output (fp16, GEMM2 input)
__device__ __align__(256) float  g_y[(size_t)NN * HC];    // layer-2 output (fp32, pool input)
__device__ __align__(256) __half g_xh[(size_t)NN * FIN];  // x converted to fp16
__device__ __align__(256) __half g_wt1[HC * FIN];         // W1^T fp16 [n][k]
__device__ __align__(256) __half g_wt2[HC * HC];          // W2^T fp16 [n][k]
__device__ float4 g_as[NN];
__device__ float4 g_ad[NN];
__device__ int    g_srcsort[ET];
__device__ int    g_deg[NN];
__device__ int    g_rowptr[NN + 1];
__device__ int    g_cursor[NN];
__device__ __align__(256) float  g_pooled[NG * HC];
__device__ int    g_src[EE];
__device__ int    g_dst[EE];
__device__ int    g_batch[NN];
__device__ int    g_is64;
#define SCAN_B 256
#define NB ((NN + SCAN_B - 1) / SCAN_B)    // 196
__device__ int    g_bsum[NB];
__device__ int    g_boff[NB];

// ---------------- dtype detect ------------------------------------------------
__global__ void detect_kernel(const unsigned* __restrict__ eiw, int* __restrict__ is64) {
    __shared__ int s_any;
    if (threadIdx.x == 0) s_any = 0;
    __syncthreads();
    unsigned v = eiw[threadIdx.x * 2 + 1];
    if (v != 0u) atomicOr(&s_any, 1);
    __syncthreads();
    if (threadIdx.x == 0) *is64 = s_any ? 0 : 1;
}

// ------- preconvert: x->fp16, W1/W2 -> transposed fp16, deg=1 (self loop) -----
__global__ void preconv_kernel(const float* __restrict__ x,
                               const float* __restrict__ W1,
                               const float* __restrict__ W2,
                               __half* __restrict__ xh,
                               __half* __restrict__ wt1,
                               __half* __restrict__ wt2,
                               int* __restrict__ deg) {
    int i = blockIdx.x * blockDim.x + threadIdx.x;
    int i4 = i * 4;
    if (i4 < NN * FIN) {
        float4 v = *(const float4*)(x + i4);
        __half2* o = (__half2*)(xh + i4);
        o[0] = __floats2half2_rn(v.x, v.y);
        o[1] = __floats2half2_rn(v.z, v.w);
    }
    if (i < NN) deg[i] = 1;
    if (i < HC * HC) {
        int n = i >> 8, k = i & 255;
        wt2[n * HC + k] = __float2half_rn(W2[k * HC + n]);
    }
    if (i < HC * FIN) {
        int n = i / FIN, k = i % FIN;
        wt1[n * FIN + k] = __float2half_rn(W1[k * HC + n]);
    }
}

// ---------------- prep: index conversion + batch + degree count ----------------
__global__ void prep_kernel(const void* __restrict__ ei, const void* __restrict__ b,
                            const int* __restrict__ is64,
                            int* __restrict__ src, int* __restrict__ dst,
                            int* __restrict__ batch, int* __restrict__ deg) {
    int i = blockIdx.x * blockDim.x + threadIdx.x;
    int w = *is64;
    if (i < EE) {
        int s, d;
        if (w) {
            const long long* p = (const long long*)ei;
            s = (int)p[i];
            d = (int)p[EE + i];
        } else {
            const int* p = (const int*)ei;
            s = p[i];
            d = p[EE + i];
        }
        src[i] = s;
        dst[i] = d;
        atomicAdd(&deg[d], 1);
    }
    if (i < NN) {
        batch[i] = w ? (int)((const long long*)b)[i] : ((const int*)b)[i];
    }
}

// ---------------- hierarchical scan -------------------------------------------
__global__ void blocksum_kernel(const int* __restrict__ deg, int* __restrict__ bsum) {
    __shared__ int sd[SCAN_B];
    int tid = threadIdx.x;
    int i = blockIdx.x * SCAN_B + tid;
    sd[tid] = (i < NN) ? deg[i] : 0;
    __syncthreads();
    for (int off = SCAN_B / 2; off; off >>= 1) {
        if (tid < off) sd[tid] += sd[tid + off];
        __syncthreads();
    }
    if (tid == 0) bsum[blockIdx.x] = sd[0];
}

__global__ void scanb_kernel(const int* __restrict__ bsum, int* __restrict__ boff) {
    __shared__ int sd[256];
    int tid = threadIdx.x;
    int v = (tid < NB) ? bsum[tid] : 0;
    sd[tid] = v;
    __syncthreads();
    for (int off = 1; off < 256; off <<= 1) {
        int t = (tid >= off) ? sd[tid - off] : 0;
        __syncthreads();
        sd[tid] += t;
        __syncthreads();
    }
    if (tid < NB) boff[tid] = sd[tid] - v;
}

__global__ void scatter_kernel(const int* __restrict__ deg, const int* __restrict__ boff,
                               int* __restrict__ rowptr, int* __restrict__ cursor) {
    __shared__ int sd[SCAN_B];
    int tid = threadIdx.x;
    int i = blockIdx.x * SCAN_B + tid;
    int v = (i < NN) ? deg[i] : 0;
    sd[tid] = v;
    __syncthreads();
    for (int off = 1; off < SCAN_B; off <<= 1) {
        int t = (tid >= off) ? sd[tid - off] : 0;
        __syncthreads();
        sd[tid] += t;
        __syncthreads();
    }
    int base = boff[blockIdx.x];
    if (i < NN) {
        rowptr[i + 1] = base + sd[tid];
        cursor[i] = base + sd[tid] - v;
    }
    if (i == 0) rowptr[0] = 0;
}

__global__ void fill_kernel(const int* __restrict__ esrc, const int* __restrict__ edst,
                            int* __restrict__ cursor, int* __restrict__ srcsort) {
    int eid = blockIdx.x * blockDim.x + threadIdx.x;
    if (eid >= ET) return;
    int s, d;
    if (eid < EE) { s = esrc[eid]; d = edst[eid]; }
    else          { s = eid - EE; d = s; }
    int pos = atomicAdd(&cursor[d], 1);
    srcsort[pos] = s;
}

// ---------------- fp16 tensor-core GEMM: C = A[M,K] @ Bt[n][k]^T ---------------
// 128x128 block, 8 warps x (32M x 64N), BK=16 double-buffered, mma.m16n8k16.f16
#define BM 128
#define BN 128
#define HS 24          // smem row stride (halves): conflict-free fragment loads

__global__ __launch_bounds__(256) void hgemm_kernel(const __half* __restrict__ A,
                                                    const __half* __restrict__ Bt,
                                                    __half* __restrict__ C,
                                                    int M, int K) {
    __shared__ __half As[2][BM * HS];
    __shared__ __half Bs[2][BM * HS];

    int tid = threadIdx.x;
    int warp = tid >> 5, lane = tid & 31;
    int warpM = (warp & 3) * 32;
    int warpN = (warp >> 2) * 64;
    int rowBase = blockIdx.y * BM;
    int colBase = blockIdx.x * BN;

    int fr = tid >> 1;          // 0..127
    int fk = (tid & 1) * 8;     // 0 or 8
    int gr = rowBase + fr;
    const uint4 z4 = make_uint4(0u, 0u, 0u, 0u);

    uint4 av, bv;

    // prologue -> buf 0
    av = (gr < M) ? *(const uint4*)(A + (size_t)gr * K + fk) : z4;
    bv = *(const uint4*)(Bt + (size_t)(colBase + fr) * K + fk);
    *(uint4*)(&As[0][fr * HS + fk]) = av;
    *(uint4*)(&Bs[0][fr * HS + fk]) = bv;
    __syncthreads();

    float d[2][8][4];
#pragma unroll
    for (int i = 0; i < 2; i++)
#pragma unroll
        for (int j = 0; j < 8; j++)
#pragma unroll
            for (int q = 0; q < 4; q++) d[i][j][q] = 0.f;

    int T = K / 16;
    int lr = lane >> 2;     // 0..7
    int lc = lane & 3;      // 0..3

    for (int t = 0; t < T; t++) {
        int buf = t & 1;
        if (t + 1 < T) {
            int k0 = (t + 1) * 16;
            av = (gr < M) ? *(const uint4*)(A + (size_t)gr * K + k0 + fk) : z4;
            bv = *(const uint4*)(Bt + (size_t)(colBase + fr) * K + k0 + fk);
        }

        unsigned af[2][4], bf[8][2];
#pragma unroll
        for (int mt = 0; mt < 2; mt++) {
            int r = warpM + 16 * mt + lr;
            af[mt][0] = *(const unsigned*)(&As[buf][r * HS + 2 * lc]);
            af[mt][1] = *(const unsigned*)(&As[buf][(r + 8) * HS + 2 * lc]);
            af[mt][2] = *(const unsigned*)(&As[buf][r * HS + 2 * lc + 8]);
            af[mt][3] = *(const unsigned*)(&As[buf][(r + 8) * HS + 2 * lc + 8]);
        }
#pragma unroll
        for (int nt = 0; nt < 8; nt++) {
            int n = warpN + 8 * nt + lr;
            bf[nt][0] = *(const unsigned*)(&Bs[buf][n * HS + 2 * lc]);
            bf[nt][1] = *(const unsigned*)(&Bs[buf][n * HS + 2 * lc + 8]);
        }
#pragma unroll
        for (int mt = 0; mt < 2; mt++)
#pragma unroll
            for (int nt = 0; nt < 8; nt++) {
                asm volatile(
                    "mma.sync.aligned.m16n8k16.row.col.f32.f16.f16.f32 "
                    "{%0,%1,%2,%3}, {%4,%5,%6,%7}, {%8,%9}, {%0,%1,%2,%3};"
                    : "+f"(d[mt][nt][0]), "+f"(d[mt][nt][1]),
                      "+f"(d[mt][nt][2]), "+f"(d[mt][nt][3])
                    : "r"(af[mt][0]), "r"(af[mt][1]), "r"(af[mt][2]), "r"(af[mt][3]),
                      "r"(bf[nt][0]), "r"(bf[nt][1]));
            }

        if (t + 1 < T) {
            int nb = buf ^ 1;
            *(uint4*)(&As[nb][fr * HS + fk]) = av;
            *(uint4*)(&Bs[nb][fr * HS + fk]) = bv;
            __syncthreads();
        }
    }

    // epilogue: fp16 pairs
#pragma unroll
    for (int mt = 0; mt < 2; mt++) {
        int r0 = rowBase + warpM + 16 * mt + lr;
        int r1 = r0 + 8;
#pragma unroll
        for (int nt = 0; nt < 8; nt++) {
            int c = colBase + warpN + 8 * nt + 2 * lc;
            if (r0 < M)
                *(__half2*)(C + (size_t)r0 * HC + c) = __floats2half2_rn(d[mt][nt][0], d[mt][nt][1]);
            if (r1 < M)
                *(__half2*)(C + (size_t)r1 * HC + c) = __floats2half2_rn(d[mt][nt][2], d[mt][nt][3]);
        }
    }
}

// ---------------- per-node attention logits (fp16 h) ---------------------------
__global__ void asad_kernel(const __half* __restrict__ hh,
                            const float* __restrict__ att_src,
                            const float* __restrict__ att_dst,
                            float4* __restrict__ as_out,
                            float4* __restrict__ ad_out) {
    int warp = (blockIdx.x * blockDim.x + threadIdx.x) >> 5;
    int lid = threadIdx.x & 31;
    if (warp >= NN) return;
    const __half2* hr = (const __half2*)(hh + (size_t)warp * HC);
    float ps[4], pd[4];
#pragma unroll
    for (int k = 0; k < 4; k++) { ps[k] = 0.f; pd[k] = 0.f; }
#pragma unroll
    for (int k = 0; k < 4; k++) {
        float2 v = __half22float2(hr[lid + 32 * k]);
        int c = 2 * lid + 64 * k;
        float2 s2 = *(const float2*)(att_src + c);
        float2 d2 = *(const float2*)(att_dst + c);
        ps[k] = fmaf(v.x, s2.x, fmaf(v.y, s2.y, ps[k]));
        pd[k] = fmaf(v.x, d2.x, fmaf(v.y, d2.y, pd[k]));
    }
#pragma unroll
    for (int off = 16; off; off >>= 1) {
#pragma unroll
        for (int k = 0; k < 4; k++) {
            ps[k] += __shfl_xor_sync(0xFFFFFFFFu, ps[k], off);
            pd[k] += __shfl_xor_sync(0xFFFFFFFFu, pd[k], off);
        }
    }
    if (lid == 0) {
        as_out[warp] = make_float4(ps[0], ps[1], ps[2], ps[3]);
        ad_out[warp] = make_float4(pd[0], pd[1], pd[2], pd[3]);
    }
}

// ---------------- fused single-pass softmax-aggregation + bias + relu + BN -----
__device__ __forceinline__ float4 leaky4(float4 a, float4 b) {
    float4 e;
    float v;
    v = a.x + b.x; e.x = (v > 0.f) ? v : SLOPE * v;
    v = a.y + b.y; e.y = (v > 0.f) ? v : SLOPE * v;
    v = a.z + b.z; e.z = (v > 0.f) ? v : SLOPE * v;
    v = a.w + b.w; e.w = (v > 0.f) ? v : SLOPE * v;
    return e;
}

__global__ __launch_bounds__(128) void agg_kernel(const int* __restrict__ srcsort,
                                                  const __half* __restrict__ hh,
                                                  const float4* __restrict__ as_in,
                                                  const float4* __restrict__ ad_in,
                                                  const int* __restrict__ rowptr,
                                                  __half* __restrict__ yh,
                                                  float* __restrict__ y32,
                                                  const float* __restrict__ bias,
                                                  const float* __restrict__ gam,
                                                  const float* __restrict__ bet,
                                                  const float* __restrict__ rmean,
                                                  const float* __restrict__ rvar) {
    int warp = (blockIdx.x * blockDim.x + threadIdx.x) >> 5;
    int lid = threadIdx.x & 31;
    if (warp >= NN) return;
    int beg = rowptr[warp], end = rowptr[warp + 1];
    float4 ad4 = ad_in[warp];

    float accx[4] = {0.f, 0.f, 0.f, 0.f};
    float accy[4] = {0.f, 0.f, 0.f, 0.f};
    float sp[4] = {0.f, 0.f, 0.f, 0.f};

    for (int base = beg; base < end; base += 32) {
        int j = base + lid;
        bool valid = j < end;
        int src = valid ? srcsort[j] : 0;
        float4 e4 = leaky4(as_in[src], ad4);
        float4 al;
        al.x = valid ? __expf(e4.x) : 0.f;
        al.y = valid ? __expf(e4.y) : 0.f;
        al.z = valid ? __expf(e4.z) : 0.f;
        al.w = valid ? __expf(e4.w) : 0.f;
        sp[0] += al.x; sp[1] += al.y; sp[2] += al.z; sp[3] += al.w;

        int nn = min(32, end - base);
        for (int i = 0; i < nn; i++) {
            int sj   = __shfl_sync(0xFFFFFFFFu, src, i);
            float a0 = __shfl_sync(0xFFFFFFFFu, al.x, i);
            float a1 = __shfl_sync(0xFFFFFFFFu, al.y, i);
            float a2 = __shfl_sync(0xFFFFFFFFu, al.z, i);
            float a3 = __shfl_sync(0xFFFFFFFFu, al.w, i);
            const __half2* hs = (const __half2*)(hh + (size_t)sj * HC);
            float2 v0 = __half22float2(hs[lid]);
            float2 v1 = __half22float2(hs[lid + 32]);
            float2 v2 = __half22float2(hs[lid + 64]);
            float2 v3 = __half22float2(hs[lid + 96]);
            accx[0] = fmaf(v0.x, a0, accx[0]);  accy[0] = fmaf(v0.y, a0, accy[0]);
            accx[1] = fmaf(v1.x, a1, accx[1]);  accy[1] = fmaf(v1.y, a1, accy[1]);
            accx[2] = fmaf(v2.x, a2, accx[2]);  accy[2] = fmaf(v2.y, a2, accy[2]);
            accx[3] = fmaf(v3.x, a3, accx[3]);  accy[3] = fmaf(v3.y, a3, accy[3]);
        }
    }

#pragma unroll
    for (int off = 16; off; off >>= 1) {
#pragma unroll
        for (int k = 0; k < 4; k++)
            sp[k] += __shfl_xor_sync(0xFFFFFFFFu, sp[k], off);
    }
    float inv[4];
#pragma unroll
    for (int k = 0; k < 4; k++) inv[k] = 1.f / sp[k];

    size_t ob = (size_t)warp * HC;
#pragma unroll
    for (int k = 0; k < 4; k++) {
        int c = 2 * lid + 64 * k;
        float2 bi = *(const float2*)(bias + c);
        float2 ga = *(const float2*)(gam + c);
        float2 be = *(const float2*)(bet + c);
        float2 rm = *(const float2*)(rmean + c);
        float2 rv = *(const float2*)(rvar + c);
        float vx = fmaxf(accx[k] * inv[k] + bi.x, 0.f);
        float vy = fmaxf(accy[k] * inv[k] + bi.y, 0.f);
        vx = (vx - rm.x) * rsqrtf(rv.x + BNEPS) * ga.x + be.x;
        vy = (vy - rm.y) * rsqrtf(rv.y + BNEPS) * ga.y + be.y;
        *(__half2*)(yh + ob + c) = __floats2half2_rn(vx, vy);
        if (y32) *(float2*)(y32 + ob + c) = make_float2(vx, vy);
    }
}

// ---------------- pooling ------------------------------------------------------
__device__ __forceinline__ int lowerb(const int* b, int n, int key) {
    int lo = 0, hi = n;
    while (lo < hi) {
        int mid = (lo + hi) >> 1;
        if (b[mid] < key) lo = mid + 1; else hi = mid;
    }
    return lo;
}

__global__ void pool_kernel(const int* __restrict__ batch,
                            const float* __restrict__ y,
                            float* __restrict__ pooled) {
    int g = blockIdx.x;
    int c = threadIdx.x;
    __shared__ int s_lo, s_hi;
    if (c == 0) {
        s_lo = lowerb(batch, NN, g);
        s_hi = lowerb(batch, NN, g + 1);
    }
    __syncthreads();
    float sum = 0.f;
    for (int n = s_lo; n < s_hi; n++) sum += y[(size_t)n * HC + c];
    int cnt = s_hi - s_lo;
    float denom = (cnt > 0) ? (float)cnt : 1.f;
    pooled[g * HC + c] = sum / denom;
}

// ---------------- MLP head -----------------------------------------------------
__global__ void head_kernel(const float* __restrict__ pooled,
                            const float* __restrict__ lw1, const float* __restrict__ lb1,
                            const float* __restrict__ lw2, const float* __restrict__ lb2,
                            float* __restrict__ out) {
    int g = blockIdx.x;
    int j = threadIdx.x;
    __shared__ float sp[256];
    __shared__ float r0[128], r1[128];
    sp[j] = pooled[g * HC + j];
    sp[j + 128] = pooled[g * HC + 128 + j];
    __syncthreads();
    float z = lb1[j];
#pragma unroll 4
    for (int k = 0; k < 256; k++) z = fmaf(sp[k], lw1[k * 128 + j], z);
    z = fmaxf(z, 0.f);
    r0[j] = z * lw2[j * 2 + 0];
    r1[j] = z * lw2[j * 2 + 1];
    __syncthreads();
    for (int off = 64; off; off >>= 1) {
        if (j < off) { r0[j] += r0[j + off]; r1[j] += r1[j + off]; }
        __syncthreads();
    }
    if (j == 0) {
        out[g * 2 + 0] = r0[0] + lb2[0];
        out[g * 2 + 1] = r1[0] + lb2[1];
    }
}

// ---------------- launcher ------------------------------------------------------
extern "C" void kernel_launch(void* const* d_in, const int* in_sizes, int n_in,
                              void* d_out, int out_size) {
    const float* x        = (const float*)d_in[0];
    const void*  ei       = d_in[1];
    const void*  batchraw = d_in[2];
    const float* W1       = (const float*)d_in[3];
    const float* att_src1 = (const float*)d_in[4];
    const float* att_dst1 = (const float*)d_in[5];
    const float* b1       = (const float*)d_in[6];
    const float* g1       = (const float*)d_in[7];
    const float* be1      = (const float*)d_in[8];
    const float* rm1      = (const float*)d_in[9];
    const float* rv1      = (const float*)d_in[10];
    const float* W2       = (const float*)d_in[11];
    const float* att_src2 = (const float*)d_in[12];
    const float* att_dst2 = (const float*)d_in[13];
    const float* b2       = (const float*)d_in[14];
    const float* g2       = (const float*)d_in[15];
    const float* be2      = (const float*)d_in[16];
    const float* rm2      = (const float*)d_in[17];
    const float* rv2      = (const float*)d_in[18];
    const float* lw1      = (const float*)d_in[19];
    const float* lb1      = (const float*)d_in[20];
    const float* lw2      = (const float*)d_in[21];
    const float* lb2      = (const float*)d_in[22];

    __half* p_hh = nullptr; __half* p_yh = nullptr; float* p_y = nullptr;
    __half* p_xh = nullptr; __half* p_wt1 = nullptr; __half* p_wt2 = nullptr;
    float4* p_as = nullptr; float4* p_ad = nullptr; int* p_deg = nullptr;
    int* p_rowptr = nullptr; int* p_cursor = nullptr; int* p_srcsort = nullptr;
    float* p_pooled = nullptr; int* p_src = nullptr; int* p_dst = nullptr;
    int* p_batch = nullptr; int* p_is64 = nullptr;
    int* p_bsum = nullptr; int* p_boff = nullptr;
    cudaGetSymbolAddress((void**)&p_hh, g_hh);
    cudaGetSymbolAddress((void**)&p_yh, g_yh);
    cudaGetSymbolAddress((void**)&p_y, g_y);
    cudaGetSymbolAddress((void**)&p_xh, g_xh);
    cudaGetSymbolAddress((void**)&p_wt1, g_wt1);
    cudaGetSymbolAddress((void**)&p_wt2, g_wt2);
    cudaGetSymbolAddress((void**)&p_as, g_as);
    cudaGetSymbolAddress((void**)&p_ad, g_ad);
    cudaGetSymbolAddress((void**)&p_deg, g_deg);
    cudaGetSymbolAddress((void**)&p_rowptr, g_rowptr);
    cudaGetSymbolAddress((void**)&p_cursor, g_cursor);
    cudaGetSymbolAddress((void**)&p_srcsort, g_srcsort);
    cudaGetSymbolAddress((void**)&p_pooled, g_pooled);
    cudaGetSymbolAddress((void**)&p_src, g_src);
    cudaGetSymbolAddress((void**)&p_dst, g_dst);
    cudaGetSymbolAddress((void**)&p_batch, g_batch);
    cudaGetSymbolAddress((void**)&p_is64, g_is64);
    cudaGetSymbolAddress((void**)&p_bsum, g_bsum);
    cudaGetSymbolAddress((void**)&p_boff, g_boff);

    dim3 ggrid(HC / BN, (NN + BM - 1) / BM);
    int aggBlocks = (NN * 32 + 127) / 128;
    int warpBlocks = (NN * 32 + 255) / 256;
    int pcBlocks = (NN * FIN / 4 + 255) / 256;

    // (1) detect (2) preconv (3) prep(+count) (4) hgemm1 <- profiled sentinel
    detect_kernel<<<1, 1024>>>((const unsigned*)ei, p_is64);
    preconv_kernel<<<pcBlocks, 256>>>(x, W1, W2, p_xh, p_wt1, p_wt2, p_deg);
    prep_kernel<<<(EE + 255) / 256, 256>>>(ei, batchraw, p_is64, p_src, p_dst,
                                           p_batch, p_deg);
    hgemm_kernel<<<ggrid, 256>>>(p_xh, p_wt1, p_hh, NN, FIN);

    // hierarchical scan + fill
    blocksum_kernel<<<NB, SCAN_B>>>(p_deg, p_bsum);
    scanb_kernel<<<1, 256>>>(p_bsum, p_boff);
    scatter_kernel<<<NB, SCAN_B>>>(p_deg, p_boff, p_rowptr, p_cursor);
    fill_kernel<<<(ET + 255) / 256, 256>>>(p_src, p_dst, p_cursor, p_srcsort);

    // ---- layer 1 ----
    asad_kernel<<<warpBlocks, 256>>>(p_hh, att_src1, att_dst1, p_as, p_ad);
    agg_kernel<<<aggBlocks, 128>>>(p_srcsort, p_hh, p_as, p_ad, p_rowptr,
                                   p_yh, (float*)nullptr,
                                   b1, g1, be1, rm1, rv1);

    // ---- layer 2 ----
    hgemm_kernel<<<ggrid, 256>>>(p_yh, p_wt2, p_hh, NN, HC);
    asad_kernel<<<warpBlocks, 256>>>(p_hh, att_src2, att_dst2, p_as, p_ad);
    agg_kernel<<<aggBlocks, 128>>>(p_srcsort, p_hh, p_as, p_ad, p_rowptr,
                                   p_yh, p_y,
                                   b2, g2, be2, rm2, rv2);

    // ---- pool + head ----
    pool_kernel<<<NG, 256>>>(p_batch, p_y, p_pooled);
    head_kernel<<<NG, 128>>>(p_pooled, lw1, lb1, lw2, lb2, (float*)d_out);
}